// round 1
// baseline (speedup 1.0000x reference)
#include <cuda_runtime.h>
#include <cstdint>

// Problem dims (fixed for this dataset)
#define NROWS 8192      // N (samples)
#define NSPIN 1024      // n_spins
#define NHID  1024      // n_hidden

// GEMM tiling
#define BM 128
#define BN 128
#define BK 8
#define NTHREADS 256

// -------------------- scratch (device globals; no cudaMalloc allowed) -----
__device__ float g_h  [(size_t)NROWS * NHID];
__device__ float g_q  [(size_t)NROWS * NHID];
__device__ float g_k  [(size_t)NROWS * NHID];
__device__ float g_v  [(size_t)NROWS * NHID];
__device__ float g_s  [(size_t)NROWS * NROWS];   // scores -> exp(scores - colmax), 256 MB
__device__ float g_o  [(size_t)NROWS * NHID];
__device__ float g_cm [NROWS];                   // per-column max
__device__ float g_pt [(size_t)64 * NROWS];      // partials (max / sum)
__device__ float g_ic [NROWS];                   // 1 / column sum

// -------------------- helpers ---------------------------------------------
__device__ __forceinline__ void fma_f32x2(unsigned long long& c,
                                          unsigned long long a,
                                          unsigned long long b) {
    asm("fma.rn.f32x2 %0, %1, %2, %0;" : "+l"(c) : "l"(a), "l"(b));
}
__device__ __forceinline__ float ull_lo(unsigned long long u) {
    return __uint_as_float((unsigned)(u & 0xffffffffull));
}
__device__ __forceinline__ float ull_hi(unsigned long long u) {
    return __uint_as_float((unsigned)(u >> 32));
}

// ==========================================================================
// C[M,N] = alpha * A[M,K] * B[N,K]^T (+ bias[n])      (NT, both row-major)
// FFMA2 (f32x2) inner loop; A duplicated in smem as (a,a) pairs.
// ==========================================================================
__global__ __launch_bounds__(NTHREADS, 2)
void sgemm_nt(const float* __restrict__ A, const float* __restrict__ B,
              const float* __restrict__ bias, float* __restrict__ C,
              int M, int N, int K, float alpha) {
    __shared__ float As[BK][2 * BM];   // duplicated: As[k][2m]=As[k][2m+1]=A
    __shared__ float Bs[BK][BN];

    const int tid = threadIdx.x;
    const int m0 = blockIdx.y * BM;
    const int n0 = blockIdx.x * BN;

    const int lrow = tid >> 1;          // 0..127
    const int lk4  = (tid & 1) * 4;     // 0 or 4

    const float* Aptr = A + (size_t)(m0 + lrow) * K + lk4;
    const float* Bptr = B + (size_t)(n0 + lrow) * K + lk4;

    const int ty = tid >> 4, tx = tid & 15;

    unsigned long long acc[8][4];
    #pragma unroll
    for (int i = 0; i < 8; i++)
        #pragma unroll
        for (int j = 0; j < 4; j++) acc[i][j] = 0ull;

    for (int k0 = 0; k0 < K; k0 += BK) {
        float4 av = *(const float4*)Aptr;
        float4 bv = *(const float4*)Bptr;
        Aptr += BK; Bptr += BK;

        __syncthreads();
        *(float2*)&As[lk4 + 0][2 * lrow] = make_float2(av.x, av.x);
        *(float2*)&As[lk4 + 1][2 * lrow] = make_float2(av.y, av.y);
        *(float2*)&As[lk4 + 2][2 * lrow] = make_float2(av.z, av.z);
        *(float2*)&As[lk4 + 3][2 * lrow] = make_float2(av.w, av.w);
        Bs[lk4 + 0][lrow] = bv.x;
        Bs[lk4 + 1][lrow] = bv.y;
        Bs[lk4 + 2][lrow] = bv.z;
        Bs[lk4 + 3][lrow] = bv.w;
        __syncthreads();

        #pragma unroll
        for (int kk = 0; kk < BK; kk++) {
            unsigned long long a2[8], b2[4];
            const ulonglong2* ap = (const ulonglong2*)&As[kk][2 * (ty * 8)];
            ulonglong2 t0 = ap[0], t1 = ap[1], t2 = ap[2], t3 = ap[3];
            a2[0] = t0.x; a2[1] = t0.y; a2[2] = t1.x; a2[3] = t1.y;
            a2[4] = t2.x; a2[5] = t2.y; a2[6] = t3.x; a2[7] = t3.y;
            const ulonglong2* bp = (const ulonglong2*)&Bs[kk][tx * 8];
            ulonglong2 u0 = bp[0], u1 = bp[1];
            b2[0] = u0.x; b2[1] = u0.y; b2[2] = u1.x; b2[3] = u1.y;
            #pragma unroll
            for (int i = 0; i < 8; i++)
                #pragma unroll
                for (int j = 0; j < 4; j++)
                    fma_f32x2(acc[i][j], a2[i], b2[j]);
        }
    }

    #pragma unroll
    for (int i = 0; i < 8; i++) {
        float* crow = C + (size_t)(m0 + ty * 8 + i) * N + n0 + tx * 8;
        #pragma unroll
        for (int j = 0; j < 4; j++) {
            float lo = ull_lo(acc[i][j]) * alpha;
            float hi = ull_hi(acc[i][j]) * alpha;
            if (bias) {
                lo += bias[n0 + tx * 8 + 2 * j];
                hi += bias[n0 + tx * 8 + 2 * j + 1];
            }
            *(float2*)(crow + 2 * j) = make_float2(lo, hi);
        }
    }
}

// ==========================================================================
// C[M,N] = A[M,K] * diag(scale[k]) * B[K,N]           (NN, row-major)
// Used for out = E @ (V rows scaled by 1/colsum).
// ==========================================================================
__global__ __launch_bounds__(NTHREADS, 2)
void sgemm_nn_scaled(const float* __restrict__ A, const float* __restrict__ B,
                     const float* __restrict__ scale, float* __restrict__ C,
                     int M, int N, int K) {
    __shared__ float As[BK][2 * BM];
    __shared__ float Bs[BK][BN];

    const int tid = threadIdx.x;
    const int m0 = blockIdx.y * BM;
    const int n0 = blockIdx.x * BN;

    const int lrow = tid >> 1;
    const int lk4  = (tid & 1) * 4;
    const float* Aptr = A + (size_t)(m0 + lrow) * K + lk4;

    const int lk = tid >> 5;            // 0..7
    const int ln = (tid & 31) * 4;      // 0..124

    const int ty = tid >> 4, tx = tid & 15;

    unsigned long long acc[8][4];
    #pragma unroll
    for (int i = 0; i < 8; i++)
        #pragma unroll
        for (int j = 0; j < 4; j++) acc[i][j] = 0ull;

    for (int k0 = 0; k0 < K; k0 += BK) {
        float4 av = *(const float4*)Aptr;
        Aptr += BK;
        float4 bv = *(const float4*)(B + (size_t)(k0 + lk) * N + n0 + ln);
        float sc = scale[k0 + lk];

        __syncthreads();
        *(float2*)&As[lk4 + 0][2 * lrow] = make_float2(av.x, av.x);
        *(float2*)&As[lk4 + 1][2 * lrow] = make_float2(av.y, av.y);
        *(float2*)&As[lk4 + 2][2 * lrow] = make_float2(av.z, av.z);
        *(float2*)&As[lk4 + 3][2 * lrow] = make_float2(av.w, av.w);
        Bs[lk][ln + 0] = bv.x * sc;
        Bs[lk][ln + 1] = bv.y * sc;
        Bs[lk][ln + 2] = bv.z * sc;
        Bs[lk][ln + 3] = bv.w * sc;
        __syncthreads();

        #pragma unroll
        for (int kk = 0; kk < BK; kk++) {
            unsigned long long a2[8], b2[4];
            const ulonglong2* ap = (const ulonglong2*)&As[kk][2 * (ty * 8)];
            ulonglong2 t0 = ap[0], t1 = ap[1], t2 = ap[2], t3 = ap[3];
            a2[0] = t0.x; a2[1] = t0.y; a2[2] = t1.x; a2[3] = t1.y;
            a2[4] = t2.x; a2[5] = t2.y; a2[6] = t3.x; a2[7] = t3.y;
            const ulonglong2* bp = (const ulonglong2*)&Bs[kk][tx * 8];
            ulonglong2 u0 = bp[0], u1 = bp[1];
            b2[0] = u0.x; b2[1] = u0.y; b2[2] = u1.x; b2[3] = u1.y;
            #pragma unroll
            for (int i = 0; i < 8; i++)
                #pragma unroll
                for (int j = 0; j < 4; j++)
                    fma_f32x2(acc[i][j], a2[i], b2[j]);
        }
    }

    #pragma unroll
    for (int i = 0; i < 8; i++) {
        float* crow = C + (size_t)(m0 + ty * 8 + i) * N + n0 + tx * 8;
        #pragma unroll
        for (int j = 0; j < 4; j++)
            *(float2*)(crow + 2 * j) = make_float2(ull_lo(acc[i][j]), ull_hi(acc[i][j]));
    }
}

// ==========================================================================
// Column softmax helpers (softmax over axis 0: normalize each column)
// ==========================================================================
#define ROWS_PER_BLK 128   // 8192 / 64

__global__ void colmax_part(const float* __restrict__ S, float* __restrict__ part) {
    int j = blockIdx.x * 256 + threadIdx.x;
    int r0 = blockIdx.y * ROWS_PER_BLK;
    const float* p = S + (size_t)r0 * NROWS + j;
    float m = -3.402823e38f;
    #pragma unroll 8
    for (int i = 0; i < ROWS_PER_BLK; i++)
        m = fmaxf(m, p[(size_t)i * NROWS]);
    part[(size_t)blockIdx.y * NROWS + j] = m;
}

__global__ void colmax_fin(const float* __restrict__ part, float* __restrict__ cm) {
    int j = blockIdx.x * 256 + threadIdx.x;
    float m = -3.402823e38f;
    #pragma unroll
    for (int i = 0; i < 64; i++)
        m = fmaxf(m, part[(size_t)i * NROWS + j]);
    cm[j] = m;
}

// overwrite S with exp(S - colmax); accumulate partial column sums
__global__ void expsum_part(float* __restrict__ S, const float* __restrict__ cm,
                            float* __restrict__ part) {
    int j = blockIdx.x * 256 + threadIdx.x;
    int r0 = blockIdx.y * ROWS_PER_BLK;
    float* p = S + (size_t)r0 * NROWS + j;
    float mj = cm[j];
    float c = 0.f;
    #pragma unroll 4
    for (int i = 0; i < ROWS_PER_BLK; i++) {
        float e = __expf(p[(size_t)i * NROWS] - mj);
        p[(size_t)i * NROWS] = e;
        c += e;
    }
    part[(size_t)blockIdx.y * NROWS + j] = c;
}

__global__ void invsum_fin(const float* __restrict__ part, float* __restrict__ ic) {
    int j = blockIdx.x * 256 + threadIdx.x;
    float c = 0.f;
    #pragma unroll
    for (int i = 0; i < 64; i++)
        c += part[(size_t)i * NROWS + j];
    ic[j] = 1.f / c;
}

// ==========================================================================
// Final: out[i] = sum_h logcosh(O[i,h]),  logcosh(z)=|z|+log1p(exp(-2|z|))-ln2
// ==========================================================================
__global__ void logcosh_rows(const float* __restrict__ O, float* __restrict__ out) {
    __shared__ float red[256];
    int row = blockIdx.x;
    const float* o = O + (size_t)row * NHID;
    float s = 0.f;
    for (int h = threadIdx.x; h < NHID; h += 256) {
        float a = fabsf(o[h]);
        s += a + log1pf(__expf(-2.f * a));
    }
    red[threadIdx.x] = s;
    __syncthreads();
    for (int st = 128; st > 0; st >>= 1) {
        if (threadIdx.x < st) red[threadIdx.x] += red[threadIdx.x + st];
        __syncthreads();
    }
    if (threadIdx.x == 0)
        out[row] = red[0] - (float)NHID * 0.69314718055994531f;
}

// ==========================================================================
extern "C" void kernel_launch(void* const* d_in, const int* in_sizes, int n_in,
                              void* d_out, int out_size) {
    const float* x   = (const float*)d_in[0];
    const float* Win = (const float*)d_in[1];
    const float* bin = (const float*)d_in[2];
    const float* Wq  = (const float*)d_in[3];
    const float* Wk  = (const float*)d_in[4];
    const float* Wv  = (const float*)d_in[5];
    float* out = (float*)d_out;

    float *h, *q, *kk, *v, *s, *o, *cm, *pt, *ic;
    cudaGetSymbolAddress((void**)&h,  g_h);
    cudaGetSymbolAddress((void**)&q,  g_q);
    cudaGetSymbolAddress((void**)&kk, g_k);
    cudaGetSymbolAddress((void**)&v,  g_v);
    cudaGetSymbolAddress((void**)&s,  g_s);
    cudaGetSymbolAddress((void**)&o,  g_o);
    cudaGetSymbolAddress((void**)&cm, g_cm);
    cudaGetSymbolAddress((void**)&pt, g_pt);
    cudaGetSymbolAddress((void**)&ic, g_ic);

    dim3 blk(NTHREADS);

    // h = x @ W_in^T + b_in
    sgemm_nt<<<dim3(NHID / BN, NROWS / BM), blk>>>(x, Win, bin, h,
                                                   NROWS, NHID, NSPIN, 1.f);
    // q,k,v = h @ W{q,k,v}^T
    sgemm_nt<<<dim3(NHID / BN, NROWS / BM), blk>>>(h, Wq, nullptr, q,
                                                   NROWS, NHID, NHID, 1.f);
    sgemm_nt<<<dim3(NHID / BN, NROWS / BM), blk>>>(h, Wk, nullptr, kk,
                                                   NROWS, NHID, NHID, 1.f);
    sgemm_nt<<<dim3(NHID / BN, NROWS / BM), blk>>>(h, Wv, nullptr, v,
                                                   NROWS, NHID, NHID, 1.f);
    // scores = 0.25 * q @ k^T
    sgemm_nt<<<dim3(NROWS / BN, NROWS / BM), blk>>>(q, kk, nullptr, s,
                                                    NROWS, NROWS, NHID, 0.25f);
    // column softmax pieces
    colmax_part<<<dim3(NROWS / 256, 64), blk>>>(s, pt);
    colmax_fin <<<NROWS / 256, blk>>>(pt, cm);
    expsum_part<<<dim3(NROWS / 256, 64), blk>>>(s, cm, pt);
    invsum_fin <<<NROWS / 256, blk>>>(pt, ic);
    // out = E @ diag(1/c) @ v
    sgemm_nn_scaled<<<dim3(NHID / BN, NROWS / BM), blk>>>(s, v, ic, o,
                                                          NROWS, NHID, NROWS);
    // per-row logcosh sum
    logcosh_rows<<<NROWS, blk>>>(o, out);
}

// round 3
// speedup vs baseline: 3.3170x; 3.3170x over previous
#include <cuda_runtime.h>
#include <cstdint>

#define NROWS 8192
#define NSPIN 1024
#define NHID  1024

// ------------------------ scratch ------------------------
__device__ float g_h [(size_t)NROWS * NHID];
__device__ float g_q [(size_t)NROWS * NHID];
__device__ float g_k [(size_t)NROWS * NHID];
__device__ float g_v [(size_t)NROWS * NHID];
__device__ float g_vt[(size_t)NROWS * NHID];     // v^T scaled by 1/colsum
__device__ float g_s [(size_t)NROWS * NROWS];    // scores -> exp(s - colmax)
__device__ float g_o [(size_t)NROWS * NHID];
__device__ float g_cm[NROWS];
__device__ float g_pt[(size_t)64 * NROWS];
__device__ float g_ic[NROWS];

// ------------------------ generic helpers ------------------------
__device__ __forceinline__ void fma_f32x2(unsigned long long& c,
                                          unsigned long long a,
                                          unsigned long long b) {
    asm("fma.rn.f32x2 %0, %1, %2, %0;" : "+l"(c) : "l"(a), "l"(b));
}
__device__ __forceinline__ float ull_lo(unsigned long long u) {
    return __uint_as_float((unsigned)(u & 0xffffffffull));
}
__device__ __forceinline__ float ull_hi(unsigned long long u) {
    return __uint_as_float((unsigned)(u >> 32));
}

#define SM103A_PATH (defined(__CUDA_ARCH__) && defined(__CUDA_ARCH_FEAT_SM103_ALL))

#if SM103A_PATH
// ------------------------ tcgen05 PTX helpers (sm_103a only) -------------
__device__ __forceinline__ uint32_t smem_u32(const void* p) {
    uint32_t a;
    asm("{ .reg .u64 t; cvta.to.shared.u64 t, %1; cvt.u32.u64 %0, t; }"
        : "=r"(a) : "l"(p));
    return a;
}
__device__ __forceinline__ uint32_t elect_one() {
    uint32_t p;
    asm volatile("{\n\t.reg .pred p;\n\telect.sync _|p, 0xFFFFFFFF;\n\t"
                 "selp.b32 %0, 1, 0, p;\n\t}" : "=r"(p));
    return p;
}
__device__ __forceinline__ uint32_t swz128(uint32_t off) {
    return off ^ ((off >> 3) & 0x70);
}
__device__ __forceinline__ float to_tf32(float x) {
    float r; asm("cvt.rna.tf32.f32 %0, %1;" : "=f"(r) : "f"(x)); return r;
}
__device__ __forceinline__ void mma_tf32(uint32_t d, uint64_t a, uint64_t b,
                                         uint32_t idesc, uint32_t en) {
    asm volatile("{\n\t.reg .pred p;\n\tsetp.ne.u32 p, %4, 0;\n\t"
                 "tcgen05.mma.cta_group::1.kind::tf32 [%0], %1, %2, %3, p;\n\t}"
                 :: "r"(d), "l"(a), "l"(b), "r"(idesc), "r"(en) : "memory");
}
#define TC_ALLOC(sa, n) \
    asm volatile("tcgen05.alloc.cta_group::1.sync.aligned.shared::cta.b32 [%0], %1;" \
                 :: "r"(sa), "r"(n) : "memory")
#define TC_RELINQ() \
    asm volatile("tcgen05.relinquish_alloc_permit.cta_group::1.sync.aligned;")
#define TC_DEALLOC(t, n) \
    asm volatile("tcgen05.dealloc.cta_group::1.sync.aligned.b32 %0, %1;" :: "r"(t), "r"(n))
#define TC_COMMIT(mb) \
    asm volatile("tcgen05.commit.cta_group::1.mbarrier::arrive::one.shared::cluster.b64 [%0];" \
                 :: "r"(mb) : "memory")
#define TC_FENCE_AFTER()  asm volatile("tcgen05.fence::after_thread_sync;" ::: "memory")
#define TC_WAIT_LD()      asm volatile("tcgen05.wait::ld.sync.aligned;" ::: "memory")
#define FENCE_ASYNC()     asm volatile("fence.proxy.async.shared::cta;" ::: "memory")
#define MBAR_INIT(mb, c) \
    asm volatile("mbarrier.init.shared.b64 [%0], %1;" :: "r"(mb), "r"(c) : "memory")
#define MBAR_WAIT(mb, par) do {                                                  \
    asm volatile("{\n\t.reg .pred P1;\n\t"                                       \
                 "WAIT_LOOP_%=:\n\t"                                             \
                 "mbarrier.try_wait.parity.acquire.cta.shared::cta.b64 P1, [%0], %1, 0x989680;\n\t" \
                 "@P1 bra.uni WAIT_DONE_%=;\n\t"                                 \
                 "bra.uni WAIT_LOOP_%=;\n\t"                                     \
                 "WAIT_DONE_%=:\n\t}"                                            \
                 :: "r"(mb), "r"(par) : "memory");                               \
} while (0)

__device__ __forceinline__ void ldtm32(uint32_t* r, uint32_t addr) {
    asm volatile(
        "tcgen05.ld.sync.aligned.32x32b.x32.b32 "
        "{%0, %1, %2, %3, %4, %5, %6, %7, "
        " %8, %9, %10, %11, %12, %13, %14, %15, "
        " %16, %17, %18, %19, %20, %21, %22, %23, "
        " %24, %25, %26, %27, %28, %29, %30, %31}, [%32];"
        : "=r"(r[0]),  "=r"(r[1]),  "=r"(r[2]),  "=r"(r[3]),
          "=r"(r[4]),  "=r"(r[5]),  "=r"(r[6]),  "=r"(r[7]),
          "=r"(r[8]),  "=r"(r[9]),  "=r"(r[10]), "=r"(r[11]),
          "=r"(r[12]), "=r"(r[13]), "=r"(r[14]), "=r"(r[15]),
          "=r"(r[16]), "=r"(r[17]), "=r"(r[18]), "=r"(r[19]),
          "=r"(r[20]), "=r"(r[21]), "=r"(r[22]), "=r"(r[23]),
          "=r"(r[24]), "=r"(r[25]), "=r"(r[26]), "=r"(r[27]),
          "=r"(r[28]), "=r"(r[29]), "=r"(r[30]), "=r"(r[31])
        : "r"(addr));
}

// SMEM descriptor: SW128, version=1 (Blackwell), LBO=1, SBO=64 (K-major)
__device__ __forceinline__ uint64_t smem_desc(uint32_t addr) {
    return ((uint64_t)2 << 61) | ((uint64_t)1 << 46) | ((uint64_t)64 << 32) |
           ((uint64_t)1 << 16) | ((uint64_t)(addr >> 4) & 0x3FFF);
}
// idesc: dtype=f32, a=tf32, b=tf32, N=128, M=128, K-major both
#define IDESC_TF32 ((1u << 4) | (2u << 7) | (2u << 10) | (16u << 17) | (8u << 24))
#endif  // SM103A_PATH

// SMEM layout (dynamic)
#define SM_TMEM   0
#define SM_MBAR   16
#define SM_TILE   1024
#define TILE_B    16384    // 128 rows x 128 bytes (32 tf32)
#define BUF_B     (4 * TILE_B)               // Ahi, Alo, Bhi, Blo
#define GEMM_SMEM (SM_TILE + 2 * BUF_B)      // 132096

// ==========================================================================
// C[M,N] = alpha * A[M,K] @ B[N,K]^T (+ bias[n])
// sm_103a: 3xTF32 on tcgen05.  Fallback: FFMA2 SIMT GEMM (correct, slower).
// Grid: (N/128, M/128), 256 threads. K % 32 == 0.
// ==========================================================================
__global__ void __launch_bounds__(256, 1)
gemm_tc_nt(const float* __restrict__ A, const float* __restrict__ B,
           const float* __restrict__ bias, float* __restrict__ C,
           int M, int N, int K, float alpha) {
#if SM103A_PATH
    extern __shared__ char smem[];
    const uint32_t sb = smem_u32(smem);
    const int tid = threadIdx.x;
    const int wid = tid >> 5;
    const int lid = tid & 31;
    const int m0 = blockIdx.y * 128;
    const int n0 = blockIdx.x * 128;

    if (wid == 0) { TC_ALLOC(sb + SM_TMEM, 128); TC_RELINQ(); }
    if (tid == 0) { MBAR_INIT(sb + SM_MBAR, 1); MBAR_INIT(sb + SM_MBAR + 8, 1); }
    __syncthreads();
    uint32_t tmem;
    asm volatile("ld.shared.b32 %0, [%1];" : "=r"(tmem) : "r"(sb + SM_TMEM));

    uint32_t soff[4];
    const float *aP[4], *bP[4];
    #pragma unroll
    for (int i = 0; i < 4; i++) {
        int f = tid + 256 * i;
        int row = f >> 3, c4 = f & 7;
        soff[i] = swz128((uint32_t)(row * 128 + c4 * 16));
        aP[i] = A + (size_t)(m0 + row) * K + c4 * 4;
        bP[i] = B + (size_t)(n0 + row) * K + c4 * 4;
    }

    uint64_t dAhi[2], dAlo[2], dBhi[2], dBlo[2];
    #pragma unroll
    for (int b = 0; b < 2; b++) {
        uint32_t base = sb + SM_TILE + b * BUF_B;
        dAhi[b] = smem_desc(base);
        dAlo[b] = smem_desc(base + TILE_B);
        dBhi[b] = smem_desc(base + 2 * TILE_B);
        dBlo[b] = smem_desc(base + 3 * TILE_B);
    }

    const int nk = K >> 5;
    for (int k0 = 0; k0 < nk; k0++) {
        const int buf = k0 & 1;

        float4 va[4], vb[4];
        #pragma unroll
        for (int i = 0; i < 4; i++) {
            va[i] = *(const float4*)(aP[i] + k0 * 32);
            vb[i] = *(const float4*)(bP[i] + k0 * 32);
        }
        float4 ha[4], la[4], hb[4], lb[4];
        #pragma unroll
        for (int i = 0; i < 4; i++) {
            ha[i].x = to_tf32(va[i].x); la[i].x = to_tf32(va[i].x - ha[i].x);
            ha[i].y = to_tf32(va[i].y); la[i].y = to_tf32(va[i].y - ha[i].y);
            ha[i].z = to_tf32(va[i].z); la[i].z = to_tf32(va[i].z - ha[i].z);
            ha[i].w = to_tf32(va[i].w); la[i].w = to_tf32(va[i].w - ha[i].w);
            hb[i].x = to_tf32(vb[i].x); lb[i].x = to_tf32(vb[i].x - hb[i].x);
            hb[i].y = to_tf32(vb[i].y); lb[i].y = to_tf32(vb[i].y - hb[i].y);
            hb[i].z = to_tf32(vb[i].z); lb[i].z = to_tf32(vb[i].z - hb[i].z);
            hb[i].w = to_tf32(vb[i].w); lb[i].w = to_tf32(vb[i].w - hb[i].w);
        }

        if (k0 >= 2) MBAR_WAIT(sb + SM_MBAR + 8 * buf, ((k0 >> 1) - 1) & 1);

        char* base = smem + SM_TILE + buf * BUF_B;
        #pragma unroll
        for (int i = 0; i < 4; i++) {
            *(float4*)(base + soff[i])              = ha[i];
            *(float4*)(base + TILE_B + soff[i])     = la[i];
            *(float4*)(base + 2 * TILE_B + soff[i]) = hb[i];
            *(float4*)(base + 3 * TILE_B + soff[i]) = lb[i];
        }
        FENCE_ASYNC();
        __syncthreads();

        if (wid == 0 && elect_one()) {
            #pragma unroll
            for (int s = 0; s < 4; s++)
                mma_tf32(tmem, dAhi[buf] + 2 * s, dBhi[buf] + 2 * s, IDESC_TF32,
                         (k0 > 0 || s > 0) ? 1u : 0u);
            #pragma unroll
            for (int s = 0; s < 4; s++)
                mma_tf32(tmem, dAhi[buf] + 2 * s, dBlo[buf] + 2 * s, IDESC_TF32, 1u);
            #pragma unroll
            for (int s = 0; s < 4; s++)
                mma_tf32(tmem, dAlo[buf] + 2 * s, dBhi[buf] + 2 * s, IDESC_TF32, 1u);
            TC_COMMIT(sb + SM_MBAR + 8 * buf);
        }
    }

    {
        const int last = nk - 1;
        MBAR_WAIT(sb + SM_MBAR + 8 * (last & 1), ((last >> 1) & 1));
    }
    TC_FENCE_AFTER();

    if (wid < 4) {
        const int r = m0 + wid * 32 + lid;
        uint32_t d[32];
        #pragma unroll
        for (int g = 0; g < 4; g++) {
            ldtm32(d, tmem + g * 32);
            TC_WAIT_LD();
            float* crow = C + (size_t)r * N + n0 + g * 32;
            #pragma unroll
            for (int j = 0; j < 8; j++) {
                float4 o;
                o.x = __uint_as_float(d[4 * j + 0]) * alpha;
                o.y = __uint_as_float(d[4 * j + 1]) * alpha;
                o.z = __uint_as_float(d[4 * j + 2]) * alpha;
                o.w = __uint_as_float(d[4 * j + 3]) * alpha;
                if (bias) {
                    const float* bp = bias + n0 + g * 32 + 4 * j;
                    o.x += bp[0]; o.y += bp[1]; o.z += bp[2]; o.w += bp[3];
                }
                *(float4*)(crow + 4 * j) = o;
            }
        }
    }
    __syncthreads();
    if (wid == 0) TC_DEALLOC(tmem, 128);

#else  // ---------------- fallback: FFMA2 SIMT GEMM (known-correct) --------
    __shared__ float As[8][2 * 128];
    __shared__ float Bs[8][128];

    const int tid = threadIdx.x;
    const int m0 = blockIdx.y * 128;
    const int n0 = blockIdx.x * 128;

    const int lrow = tid >> 1;
    const int lk4  = (tid & 1) * 4;

    const float* Aptr = A + (size_t)(m0 + lrow) * K + lk4;
    const float* Bptr = B + (size_t)(n0 + lrow) * K + lk4;

    const int ty = tid >> 4, tx = tid & 15;

    unsigned long long acc[8][4];
    #pragma unroll
    for (int i = 0; i < 8; i++)
        #pragma unroll
        for (int j = 0; j < 4; j++) acc[i][j] = 0ull;

    for (int k0 = 0; k0 < K; k0 += 8) {
        float4 av = *(const float4*)Aptr;
        float4 bv = *(const float4*)Bptr;
        Aptr += 8; Bptr += 8;

        __syncthreads();
        *(float2*)&As[lk4 + 0][2 * lrow] = make_float2(av.x, av.x);
        *(float2*)&As[lk4 + 1][2 * lrow] = make_float2(av.y, av.y);
        *(float2*)&As[lk4 + 2][2 * lrow] = make_float2(av.z, av.z);
        *(float2*)&As[lk4 + 3][2 * lrow] = make_float2(av.w, av.w);
        Bs[lk4 + 0][lrow] = bv.x;
        Bs[lk4 + 1][lrow] = bv.y;
        Bs[lk4 + 2][lrow] = bv.z;
        Bs[lk4 + 3][lrow] = bv.w;
        __syncthreads();

        #pragma unroll
        for (int kk = 0; kk < 8; kk++) {
            unsigned long long a2[8], b2[4];
            const ulonglong2* ap = (const ulonglong2*)&As[kk][2 * (ty * 8)];
            ulonglong2 t0 = ap[0], t1 = ap[1], t2 = ap[2], t3 = ap[3];
            a2[0] = t0.x; a2[1] = t0.y; a2[2] = t1.x; a2[3] = t1.y;
            a2[4] = t2.x; a2[5] = t2.y; a2[6] = t3.x; a2[7] = t3.y;
            const ulonglong2* bp = (const ulonglong2*)&Bs[kk][tx * 8];
            ulonglong2 u0 = bp[0], u1 = bp[1];
            b2[0] = u0.x; b2[1] = u0.y; b2[2] = u1.x; b2[3] = u1.y;
            #pragma unroll
            for (int i = 0; i < 8; i++)
                #pragma unroll
                for (int j = 0; j < 4; j++)
                    fma_f32x2(acc[i][j], a2[i], b2[j]);
        }
    }

    #pragma unroll
    for (int i = 0; i < 8; i++) {
        float* crow = C + (size_t)(m0 + ty * 8 + i) * N + n0 + tx * 8;
        #pragma unroll
        for (int j = 0; j < 4; j++) {
            float lo = ull_lo(acc[i][j]) * alpha;
            float hi = ull_hi(acc[i][j]) * alpha;
            if (bias) {
                lo += bias[n0 + tx * 8 + 2 * j];
                hi += bias[n0 + tx * 8 + 2 * j + 1];
            }
            *(float2*)(crow + 2 * j) = make_float2(lo, hi);
        }
    }
#endif
}

// ==========================================================================
// Column softmax helpers (softmax over axis 0)
// ==========================================================================
#define ROWS_PER_BLK 128

__global__ void colmax_part(const float* __restrict__ S, float* __restrict__ part) {
    int j = blockIdx.x * 256 + threadIdx.x;
    int r0 = blockIdx.y * ROWS_PER_BLK;
    const float* p = S + (size_t)r0 * NROWS + j;
    float m = -3.402823e38f;
    #pragma unroll 8
    for (int i = 0; i < ROWS_PER_BLK; i++)
        m = fmaxf(m, p[(size_t)i * NROWS]);
    part[(size_t)blockIdx.y * NROWS + j] = m;
}

__global__ void colmax_fin(const float* __restrict__ part, float* __restrict__ cm) {
    int j = blockIdx.x * 256 + threadIdx.x;
    float m = -3.402823e38f;
    #pragma unroll
    for (int i = 0; i < 64; i++)
        m = fmaxf(m, part[(size_t)i * NROWS + j]);
    cm[j] = m;
}

__global__ void expsum_part(float* __restrict__ S, const float* __restrict__ cm,
                            float* __restrict__ part) {
    int j = blockIdx.x * 256 + threadIdx.x;
    int r0 = blockIdx.y * ROWS_PER_BLK;
    float* p = S + (size_t)r0 * NROWS + j;
    float mj = cm[j];
    float c = 0.f;
    #pragma unroll 4
    for (int i = 0; i < ROWS_PER_BLK; i++) {
        float e = __expf(p[(size_t)i * NROWS] - mj);
        p[(size_t)i * NROWS] = e;
        c += e;
    }
    part[(size_t)blockIdx.y * NROWS + j] = c;
}

__global__ void invsum_fin(const float* __restrict__ part, float* __restrict__ ic) {
    int j = blockIdx.x * 256 + threadIdx.x;
    float c = 0.f;
    #pragma unroll
    for (int i = 0; i < 64; i++)
        c += part[(size_t)i * NROWS + j];
    ic[j] = 1.f / c;
}

// ==========================================================================
// vt[n,k] = v[k,n] * ic[k]
// ==========================================================================
__global__ void transpose_scale(const float* __restrict__ V,
                                const float* __restrict__ ic,
                                float* __restrict__ VT) {
    __shared__ float t[32][33];
    int n = blockIdx.x * 32 + threadIdx.x;
    int k = blockIdx.y * 32 + threadIdx.y;
    #pragma unroll
    for (int i = 0; i < 32; i += 8)
        t[threadIdx.y + i][threadIdx.x] = V[(size_t)(k + i) * NHID + n] * ic[k + i];
    __syncthreads();
    int ko = blockIdx.y * 32 + threadIdx.x;
    int no = blockIdx.x * 32 + threadIdx.y;
    #pragma unroll
    for (int i = 0; i < 32; i += 8)
        VT[(size_t)(no + i) * NROWS + ko] = t[threadIdx.x][threadIdx.y + i];
}

// ==========================================================================
// out[i] = sum_h logcosh(O[i,h])
// ==========================================================================
__global__ void logcosh_rows(const float* __restrict__ O, float* __restrict__ out) {
    __shared__ float red[256];
    int row = blockIdx.x;
    const float* o = O + (size_t)row * NHID;
    float s = 0.f;
    for (int h = threadIdx.x; h < NHID; h += 256) {
        float a = fabsf(o[h]);
        s += a + log1pf(__expf(-2.f * a));
    }
    red[threadIdx.x] = s;
    __syncthreads();
    for (int st = 128; st > 0; st >>= 1) {
        if (threadIdx.x < st) red[threadIdx.x] += red[threadIdx.x + st];
        __syncthreads();
    }
    if (threadIdx.x == 0)
        out[row] = red[0] - (float)NHID * 0.69314718055994531f;
}

// ==========================================================================
extern "C" void kernel_launch(void* const* d_in, const int* in_sizes, int n_in,
                              void* d_out, int out_size) {
    const float* x   = (const float*)d_in[0];
    const float* Win = (const float*)d_in[1];
    const float* bin = (const float*)d_in[2];
    const float* Wq  = (const float*)d_in[3];
    const float* Wk  = (const float*)d_in[4];
    const float* Wv  = (const float*)d_in[5];
    float* out = (float*)d_out;

    float *h, *q, *k, *v, *vt, *s, *o, *cm, *pt, *ic;
    cudaGetSymbolAddress((void**)&h,  g_h);
    cudaGetSymbolAddress((void**)&q,  g_q);
    cudaGetSymbolAddress((void**)&k,  g_k);
    cudaGetSymbolAddress((void**)&v,  g_v);
    cudaGetSymbolAddress((void**)&vt, g_vt);
    cudaGetSymbolAddress((void**)&s,  g_s);
    cudaGetSymbolAddress((void**)&o,  g_o);
    cudaGetSymbolAddress((void**)&cm, g_cm);
    cudaGetSymbolAddress((void**)&pt, g_pt);
    cudaGetSymbolAddress((void**)&ic, g_ic);

    cudaFuncSetAttribute(gemm_tc_nt, cudaFuncAttributeMaxDynamicSharedMemorySize,
                         GEMM_SMEM);

    dim3 blk(256);
    dim3 gHid(NHID / 128, NROWS / 128);    // (8, 64)
    dim3 gScr(NROWS / 128, NROWS / 128);   // (64, 64)

    gemm_tc_nt<<<gHid, blk, GEMM_SMEM>>>(x, Win, bin, h, NROWS, NHID, NSPIN, 1.f);
    gemm_tc_nt<<<gHid, blk, GEMM_SMEM>>>(h, Wq, nullptr, q, NROWS, NHID, NHID, 0.25f);
    gemm_tc_nt<<<gHid, blk, GEMM_SMEM>>>(h, Wk, nullptr, k, NROWS, NHID, NHID, 1.f);
    gemm_tc_nt<<<gHid, blk, GEMM_SMEM>>>(h, Wv, nullptr, v, NROWS, NHID, NHID, 1.f);
    gemm_tc_nt<<<gScr, blk, GEMM_SMEM>>>(q, k, nullptr, s, NROWS, NROWS, NHID, 1.f);
    colmax_part<<<dim3(NROWS / 256, 64), blk>>>(s, pt);
    colmax_fin <<<NROWS / 256, blk>>>(pt, cm);
    expsum_part<<<dim3(NROWS / 256, 64), blk>>>(s, cm, pt);
    invsum_fin <<<NROWS / 256, blk>>>(pt, ic);
    transpose_scale<<<dim3(NHID / 32, NROWS / 32), dim3(32, 8)>>>(v, ic, vt);
    gemm_tc_nt<<<gHid, blk, GEMM_SMEM>>>(s, vt, nullptr, o, NROWS, NHID, NROWS, 1.f);
    logcosh_rows<<<NROWS, blk>>>(o, out);
}

// round 4
// speedup vs baseline: 4.7507x; 1.4323x over previous
#include <cuda_runtime.h>
#include <cstdint>

#define NROWS 8192
#define NSPIN 1024
#define NHID  1024
#define KC    32
#define MT    128
#define NT    256

// ------------------------ scratch (device globals) ------------------------
__device__ float g_xhi[(size_t)NROWS * NSPIN];
__device__ float g_xlo[(size_t)NROWS * NSPIN];
__device__ float g_wihi[(size_t)NHID * NSPIN];
__device__ float g_wilo[(size_t)NHID * NSPIN];
__device__ float g_wqhi[(size_t)NHID * NHID];
__device__ float g_wqlo[(size_t)NHID * NHID];
__device__ float g_wkhi[(size_t)NHID * NHID];
__device__ float g_wklo[(size_t)NHID * NHID];
__device__ float g_wvhi[(size_t)NHID * NHID];
__device__ float g_wvlo[(size_t)NHID * NHID];
__device__ float g_hhi[(size_t)NROWS * NHID];
__device__ float g_hlo[(size_t)NROWS * NHID];
__device__ float g_qhi[(size_t)NROWS * NHID];
__device__ float g_qlo[(size_t)NROWS * NHID];
__device__ float g_khi[(size_t)NROWS * NHID];
__device__ float g_klo[(size_t)NROWS * NHID];
__device__ float g_v  [(size_t)NROWS * NHID];
__device__ float g_vthi[(size_t)NROWS * NHID];
__device__ float g_vtlo[(size_t)NROWS * NHID];
__device__ float g_s  [(size_t)NROWS * NROWS];   // scores -> E_hi (in place)
__device__ float g_elo[(size_t)NROWS * NROWS];   // E_lo
__device__ float g_o  [(size_t)NROWS * NHID];
__device__ float g_cm [NROWS];
__device__ float g_pt [(size_t)64 * NROWS];
__device__ float g_ic [NROWS];

// ------------------------ portable helpers ------------------------
// rna tf32 rounding without arch-gated cvt (safe on all compile passes)
__device__ __forceinline__ float tf32_rna(float x) {
    uint32_t u = __float_as_uint(x);
    u = (u + 0x1000u) & 0xFFFFE000u;
    return __uint_as_float(u);
}

#define SM103A_PATH (defined(__CUDA_ARCH__) && defined(__CUDA_ARCH_FEAT_SM103_ALL))

#if SM103A_PATH
__device__ __forceinline__ uint32_t smem_u32(const void* p) {
    uint32_t a;
    asm("{ .reg .u64 t; cvta.to.shared.u64 t, %1; cvt.u32.u64 %0, t; }"
        : "=r"(a) : "l"(p));
    return a;
}
__device__ __forceinline__ uint32_t elect_one() {
    uint32_t p;
    asm volatile("{\n\t.reg .pred p;\n\telect.sync _|p, 0xFFFFFFFF;\n\t"
                 "selp.b32 %0, 1, 0, p;\n\t}" : "=r"(p));
    return p;
}
__device__ __forceinline__ uint32_t swz128(uint32_t off) {
    return off ^ ((off >> 3) & 0x70);
}
__device__ __forceinline__ void mma_tf32(uint32_t d, uint64_t a, uint64_t b,
                                         uint32_t idesc, uint32_t en) {
    asm volatile("{\n\t.reg .pred p;\n\tsetp.ne.u32 p, %4, 0;\n\t"
                 "tcgen05.mma.cta_group::1.kind::tf32 [%0], %1, %2, %3, p;\n\t}"
                 :: "r"(d), "l"(a), "l"(b), "r"(idesc), "r"(en) : "memory");
}
__device__ __forceinline__ void cpa16(uint32_t dst, const void* src) {
    asm volatile("cp.async.cg.shared.global [%0], [%1], 16;"
                 :: "r"(dst), "l"(src) : "memory");
}
#define CP_COMMIT() asm volatile("cp.async.commit_group;" ::: "memory")
#define CP_WAIT0()  asm volatile("cp.async.wait_group 0;" ::: "memory")
#define TC_ALLOC(sa, n) \
    asm volatile("tcgen05.alloc.cta_group::1.sync.aligned.shared::cta.b32 [%0], %1;" \
                 :: "r"(sa), "r"(n) : "memory")
#define TC_RELINQ() \
    asm volatile("tcgen05.relinquish_alloc_permit.cta_group::1.sync.aligned;")
#define TC_DEALLOC(t, n) \
    asm volatile("tcgen05.dealloc.cta_group::1.sync.aligned.b32 %0, %1;" :: "r"(t), "r"(n))
#define TC_COMMIT(mb) \
    asm volatile("tcgen05.commit.cta_group::1.mbarrier::arrive::one.shared::cluster.b64 [%0];" \
                 :: "r"(mb) : "memory")
#define TC_FENCE_AFTER()  asm volatile("tcgen05.fence::after_thread_sync;" ::: "memory")
#define TC_WAIT_LD()      asm volatile("tcgen05.wait::ld.sync.aligned;" ::: "memory")
#define FENCE_ASYNC()     asm volatile("fence.proxy.async.shared::cta;" ::: "memory")
#define MBAR_INIT(mb, c) \
    asm volatile("mbarrier.init.shared.b64 [%0], %1;" :: "r"(mb), "r"(c) : "memory")
#define MBAR_WAIT(mb, par) do {                                                  \
    asm volatile("{\n\t.reg .pred P1;\n\t"                                       \
                 "WAIT_LOOP_%=:\n\t"                                             \
                 "mbarrier.try_wait.parity.acquire.cta.shared::cta.b64 P1, [%0], %1, 0x989680;\n\t" \
                 "@P1 bra.uni WAIT_DONE_%=;\n\t"                                 \
                 "bra.uni WAIT_LOOP_%=;\n\t"                                     \
                 "WAIT_DONE_%=:\n\t}"                                            \
                 :: "r"(mb), "r"(par) : "memory");                               \
} while (0)

__device__ __forceinline__ void ldtm32(uint32_t* r, uint32_t addr) {
    asm volatile(
        "tcgen05.ld.sync.aligned.32x32b.x32.b32 "
        "{%0, %1, %2, %3, %4, %5, %6, %7, "
        " %8, %9, %10, %11, %12, %13, %14, %15, "
        " %16, %17, %18, %19, %20, %21, %22, %23, "
        " %24, %25, %26, %27, %28, %29, %30, %31}, [%32];"
        : "=r"(r[0]),  "=r"(r[1]),  "=r"(r[2]),  "=r"(r[3]),
          "=r"(r[4]),  "=r"(r[5]),  "=r"(r[6]),  "=r"(r[7]),
          "=r"(r[8]),  "=r"(r[9]),  "=r"(r[10]), "=r"(r[11]),
          "=r"(r[12]), "=r"(r[13]), "=r"(r[14]), "=r"(r[15]),
          "=r"(r[16]), "=r"(r[17]), "=r"(r[18]), "=r"(r[19]),
          "=r"(r[20]), "=r"(r[21]), "=r"(r[22]), "=r"(r[23]),
          "=r"(r[24]), "=r"(r[25]), "=r"(r[26]), "=r"(r[27]),
          "=r"(r[28]), "=r"(r[29]), "=r"(r[30]), "=r"(r[31])
        : "r"(addr));
}
// SMEM descriptor: SW128, Blackwell version=1, LBO=1, SBO=64 (K-major)
__device__ __forceinline__ uint64_t smem_desc(uint32_t addr) {
    return ((uint64_t)2 << 61) | ((uint64_t)1 << 46) | ((uint64_t)64 << 32) |
           ((uint64_t)1 << 16) | ((uint64_t)(addr >> 4) & 0x3FFF);
}
// idesc: dtype=f32, a=tf32, b=tf32, N=256, M=128, K-major
#define IDESC_TF32 ((1u << 4) | (2u << 7) | (2u << 10) | (32u << 17) | (8u << 24))
#endif  // SM103A_PATH

// SMEM layout
#define SM_TMEMP  0
#define SM_MB     16
#define SM_TILES  1024
#define ABYTES    16384      // 128 x 128B
#define BBYTES    32768      // 256 x 128B
#define BUFB      (2 * ABYTES + 2 * BBYTES)   // 98304
#define GSMEM     (SM_TILES + 2 * BUFB)       // 197632

// ==========================================================================
// C[M,N] = alpha * A[M,K] @ B[N,K]^T (+ bias)
// A,B given pre-split (hi/lo tf32). Optional plain out C and/or split out.
// Grid: (N/256, M/128), 256 threads.
// ==========================================================================
__global__ void __launch_bounds__(256, 1)
gemm2(const float* __restrict__ Ahi, const float* __restrict__ Alo,
      const float* __restrict__ Bhi, const float* __restrict__ Blo,
      const float* __restrict__ bias, float* __restrict__ C,
      float* __restrict__ Chi, float* __restrict__ Clo,
      int M, int N, int K, float alpha) {
#if SM103A_PATH
    extern __shared__ char smem[];
    const uint32_t sb = smem_u32(smem);
    const int tid = threadIdx.x;
    const int wid = tid >> 5;
    const int lid = tid & 31;
    const int m0 = blockIdx.y * MT;
    const int n0 = blockIdx.x * NT;

    if (wid == 0) { TC_ALLOC(sb + SM_TMEMP, 256); TC_RELINQ(); }
    if (tid == 0) { MBAR_INIT(sb + SM_MB, 1); MBAR_INIT(sb + SM_MB + 8, 1); }
    __syncthreads();
    uint32_t tmem;
    asm volatile("ld.shared.b32 %0, [%1];" : "=r"(tmem) : "r"(sb + SM_TMEMP));

    // load mapping: A 4x16B per thread, B 8x16B per thread (per hi/lo tensor)
    uint32_t dA[4], dB[8];
    const float *pAh[4], *pAl[4], *pBh[8], *pBl[8];
    #pragma unroll
    for (int i = 0; i < 4; i++) {
        int idx = tid + 256 * i, r = idx >> 3, c = idx & 7;
        dA[i] = swz128((uint32_t)(r * 128 + c * 16));
        size_t go = (size_t)(m0 + r) * K + c * 4;
        pAh[i] = Ahi + go;  pAl[i] = Alo + go;
    }
    #pragma unroll
    for (int i = 0; i < 8; i++) {
        int idx = tid + 256 * i, r = idx >> 3, c = idx & 7;
        dB[i] = swz128((uint32_t)(r * 128 + c * 16));
        size_t go = (size_t)(n0 + r) * K + c * 4;
        pBh[i] = Bhi + go;  pBl[i] = Blo + go;
    }

    const int nk = K / KC;

    // prologue: stage 0
    {
        uint32_t bb = sb + SM_TILES;
        #pragma unroll
        for (int i = 0; i < 4; i++) {
            cpa16(bb + dA[i], pAh[i]);
            cpa16(bb + ABYTES + dA[i], pAl[i]);
        }
        #pragma unroll
        for (int i = 0; i < 8; i++) {
            cpa16(bb + 2 * ABYTES + dB[i], pBh[i]);
            cpa16(bb + 2 * ABYTES + BBYTES + dB[i], pBl[i]);
        }
        CP_COMMIT();
    }

    for (int k0 = 0; k0 < nk; k0++) {
        CP_WAIT0();
        FENCE_ASYNC();
        __syncthreads();

        if (wid == 0 && elect_one()) {
            const int buf = k0 & 1;
            uint32_t tb = sb + SM_TILES + buf * BUFB;
            uint64_t dAh = smem_desc(tb);
            uint64_t dAl = smem_desc(tb + ABYTES);
            uint64_t dBh = smem_desc(tb + 2 * ABYTES);
            uint64_t dBl = smem_desc(tb + 2 * ABYTES + BBYTES);
            #pragma unroll
            for (int s = 0; s < 4; s++)
                mma_tf32(tmem, dAh + 2 * s, dBh + 2 * s, IDESC_TF32,
                         (k0 > 0 || s > 0) ? 1u : 0u);
            #pragma unroll
            for (int s = 0; s < 4; s++)
                mma_tf32(tmem, dAh + 2 * s, dBl + 2 * s, IDESC_TF32, 1u);
            #pragma unroll
            for (int s = 0; s < 4; s++)
                mma_tf32(tmem, dAl + 2 * s, dBh + 2 * s, IDESC_TF32, 1u);
            TC_COMMIT(sb + SM_MB + 8 * buf);
        }

        if (k0 + 1 < nk) {
            // buffer (k0+1)&1 was read by MMA(k0-1): wait its commit
            if (k0 >= 1)
                MBAR_WAIT(sb + SM_MB + 8 * ((k0 - 1) & 1), ((k0 - 1) >> 1) & 1);
            uint32_t bb = sb + SM_TILES + ((k0 + 1) & 1) * BUFB;
            const int off = (k0 + 1) * KC;
            #pragma unroll
            for (int i = 0; i < 4; i++) {
                cpa16(bb + dA[i], pAh[i] + off);
                cpa16(bb + ABYTES + dA[i], pAl[i] + off);
            }
            #pragma unroll
            for (int i = 0; i < 8; i++) {
                cpa16(bb + 2 * ABYTES + dB[i], pBh[i] + off);
                cpa16(bb + 2 * ABYTES + BBYTES + dB[i], pBl[i] + off);
            }
        }
        CP_COMMIT();
    }

    {
        const int last = nk - 1;
        MBAR_WAIT(sb + SM_MB + 8 * (last & 1), (last >> 1) & 1);
    }
    TC_FENCE_AFTER();

    if (wid < 4) {
        const int r = m0 + wid * 32 + lid;
        #pragma unroll
        for (int g = 0; g < 8; g++) {
            uint32_t d[32];
            ldtm32(d, tmem + g * 32);
            TC_WAIT_LD();
            const int c0 = n0 + g * 32;
            float vals[32];
            #pragma unroll
            for (int j = 0; j < 32; j++) {
                float v = __uint_as_float(d[j]) * alpha;
                if (bias) v += bias[c0 + j];
                vals[j] = v;
            }
            if (C) {
                float* crow = C + (size_t)r * N + c0;
                #pragma unroll
                for (int j = 0; j < 8; j++)
                    *(float4*)(crow + 4 * j) = make_float4(
                        vals[4 * j], vals[4 * j + 1], vals[4 * j + 2], vals[4 * j + 3]);
            }
            if (Chi) {
                float* hrow = Chi + (size_t)r * N + c0;
                float* lrow = Clo + (size_t)r * N + c0;
                #pragma unroll
                for (int j = 0; j < 8; j++) {
                    float4 hv, lv;
                    float h0 = tf32_rna(vals[4 * j + 0]), h1 = tf32_rna(vals[4 * j + 1]);
                    float h2 = tf32_rna(vals[4 * j + 2]), h3 = tf32_rna(vals[4 * j + 3]);
                    hv = make_float4(h0, h1, h2, h3);
                    lv = make_float4(tf32_rna(vals[4 * j + 0] - h0),
                                     tf32_rna(vals[4 * j + 1] - h1),
                                     tf32_rna(vals[4 * j + 2] - h2),
                                     tf32_rna(vals[4 * j + 3] - h3));
                    *(float4*)(hrow + 4 * j) = hv;
                    *(float4*)(lrow + 4 * j) = lv;
                }
            }
        }
    }
    __syncthreads();
    if (wid == 0) TC_DEALLOC(tmem, 256);

#else  // ------- fallback (compile-only for plain compute_103 pass) -------
    const int tid = threadIdx.x;
    const int m0 = blockIdx.y * MT, n0 = blockIdx.x * NT;
    int r = m0 + (tid & 127);
    int cb = n0 + (tid >> 7) * 128;
    for (int j = 0; j < 128; j++) {
        int c = cb + j;
        float acc = 0.f;
        for (int kk = 0; kk < K; kk++)
            acc += (Ahi[(size_t)r * K + kk] + Alo[(size_t)r * K + kk]) *
                   (Bhi[(size_t)c * K + kk] + Blo[(size_t)c * K + kk]);
        float v = acc * alpha + (bias ? bias[c] : 0.f);
        if (C) C[(size_t)r * N + c] = v;
        if (Chi) {
            float h = tf32_rna(v);
            Chi[(size_t)r * N + c] = h;
            Clo[(size_t)r * N + c] = tf32_rna(v - h);
        }
    }
#endif
}

// ==========================================================================
// elementwise split: in -> hi/lo tf32 pair
// ==========================================================================
__global__ void split2(const float* __restrict__ in, float* __restrict__ hi,
                       float* __restrict__ lo) {
    size_t i = ((size_t)blockIdx.x * 256 + threadIdx.x) * 4;
    float4 v = *(const float4*)(in + i);
    float4 h, l;
    h.x = tf32_rna(v.x); l.x = tf32_rna(v.x - h.x);
    h.y = tf32_rna(v.y); l.y = tf32_rna(v.y - h.y);
    h.z = tf32_rna(v.z); l.z = tf32_rna(v.z - h.z);
    h.w = tf32_rna(v.w); l.w = tf32_rna(v.w - h.w);
    *(float4*)(hi + i) = h;
    *(float4*)(lo + i) = l;
}

// ==========================================================================
// Column softmax (axis 0)
// ==========================================================================
#define ROWS_PER_BLK 128

__global__ void colmax_part(const float* __restrict__ S, float* __restrict__ part) {
    int j = blockIdx.x * 256 + threadIdx.x;
    int r0 = blockIdx.y * ROWS_PER_BLK;
    const float* p = S + (size_t)r0 * NROWS + j;
    float m = -3.402823e38f;
    #pragma unroll 8
    for (int i = 0; i < ROWS_PER_BLK; i++)
        m = fmaxf(m, p[(size_t)i * NROWS]);
    part[(size_t)blockIdx.y * NROWS + j] = m;
}

__global__ void colmax_fin(const float* __restrict__ part, float* __restrict__ cm) {
    int j = blockIdx.x * 256 + threadIdx.x;
    float m = -3.402823e38f;
    #pragma unroll
    for (int i = 0; i < 64; i++)
        m = fmaxf(m, part[(size_t)i * NROWS + j]);
    cm[j] = m;
}

// S <- hi(exp(S-colmax)) in place, ELO <- lo, partial column sums
__global__ void expsum_part(float* __restrict__ S, float* __restrict__ ELO,
                            const float* __restrict__ cm, float* __restrict__ part) {
    int j = blockIdx.x * 256 + threadIdx.x;
    int r0 = blockIdx.y * ROWS_PER_BLK;
    float* p = S + (size_t)r0 * NROWS + j;
    float* pl = ELO + (size_t)r0 * NROWS + j;
    float mj = cm[j];
    float c = 0.f;
    #pragma unroll 4
    for (int i = 0; i < ROWS_PER_BLK; i++) {
        float e = __expf(p[(size_t)i * NROWS] - mj);
        float h = tf32_rna(e);
        p [(size_t)i * NROWS] = h;
        pl[(size_t)i * NROWS] = tf32_rna(e - h);
        c += e;
    }
    part[(size_t)blockIdx.y * NROWS + j] = c;
}

__global__ void invsum_fin(const float* __restrict__ part, float* __restrict__ ic) {
    int j = blockIdx.x * 256 + threadIdx.x;
    float c = 0.f;
    #pragma unroll
    for (int i = 0; i < 64; i++)
        c += part[(size_t)i * NROWS + j];
    ic[j] = 1.f / c;
}

// ==========================================================================
// vt[n,k] = v[k,n] * ic[k], written as hi/lo split
// ==========================================================================
__global__ void transpose_scale2(const float* __restrict__ V,
                                 const float* __restrict__ ic,
                                 float* __restrict__ VTh, float* __restrict__ VTl) {
    __shared__ float t[32][33];
    int n = blockIdx.x * 32 + threadIdx.x;
    int k = blockIdx.y * 32 + threadIdx.y;
    #pragma unroll
    for (int i = 0; i < 32; i += 8)
        t[threadIdx.y + i][threadIdx.x] = V[(size_t)(k + i) * NHID + n] * ic[k + i];
    __syncthreads();
    int ko = blockIdx.y * 32 + threadIdx.x;
    int no = blockIdx.x * 32 + threadIdx.y;
    #pragma unroll
    for (int i = 0; i < 32; i += 8) {
        float v = t[threadIdx.x][threadIdx.y + i];
        float h = tf32_rna(v);
        VTh[(size_t)(no + i) * NROWS + ko] = h;
        VTl[(size_t)(no + i) * NROWS + ko] = tf32_rna(v - h);
    }
}

// ==========================================================================
// out[i] = sum_h logcosh(O[i,h])
// ==========================================================================
__global__ void logcosh_rows(const float* __restrict__ O, float* __restrict__ out) {
    __shared__ float red[256];
    int row = blockIdx.x;
    const float* o = O + (size_t)row * NHID;
    float s = 0.f;
    for (int h = threadIdx.x; h < NHID; h += 256) {
        float a = fabsf(o[h]);
        s += a + log1pf(__expf(-2.f * a));
    }
    red[threadIdx.x] = s;
    __syncthreads();
    for (int st = 128; st > 0; st >>= 1) {
        if (threadIdx.x < st) red[threadIdx.x] += red[threadIdx.x + st];
        __syncthreads();
    }
    if (threadIdx.x == 0)
        out[row] = red[0] - (float)NHID * 0.69314718055994531f;
}

// ==========================================================================
extern "C" void kernel_launch(void* const* d_in, const int* in_sizes, int n_in,
                              void* d_out, int out_size) {
    const float* x   = (const float*)d_in[0];
    const float* Win = (const float*)d_in[1];
    const float* bin = (const float*)d_in[2];
    const float* Wq  = (const float*)d_in[3];
    const float* Wk  = (const float*)d_in[4];
    const float* Wv  = (const float*)d_in[5];
    float* out = (float*)d_out;

    float *xhi, *xlo, *wihi, *wilo, *wqhi, *wqlo, *wkhi, *wklo, *wvhi, *wvlo;
    float *hhi, *hlo, *qhi, *qlo, *khi, *klo, *v, *vthi, *vtlo;
    float *s, *elo, *o, *cm, *pt, *ic;
    cudaGetSymbolAddress((void**)&xhi,  g_xhi);
    cudaGetSymbolAddress((void**)&xlo,  g_xlo);
    cudaGetSymbolAddress((void**)&wihi, g_wihi);
    cudaGetSymbolAddress((void**)&wilo, g_wilo);
    cudaGetSymbolAddress((void**)&wqhi, g_wqhi);
    cudaGetSymbolAddress((void**)&wqlo, g_wqlo);
    cudaGetSymbolAddress((void**)&wkhi, g_wkhi);
    cudaGetSymbolAddress((void**)&wklo, g_wklo);
    cudaGetSymbolAddress((void**)&wvhi, g_wvhi);
    cudaGetSymbolAddress((void**)&wvlo, g_wvlo);
    cudaGetSymbolAddress((void**)&hhi,  g_hhi);
    cudaGetSymbolAddress((void**)&hlo,  g_hlo);
    cudaGetSymbolAddress((void**)&qhi,  g_qhi);
    cudaGetSymbolAddress((void**)&qlo,  g_qlo);
    cudaGetSymbolAddress((void**)&khi,  g_khi);
    cudaGetSymbolAddress((void**)&klo,  g_klo);
    cudaGetSymbolAddress((void**)&v,    g_v);
    cudaGetSymbolAddress((void**)&vthi, g_vthi);
    cudaGetSymbolAddress((void**)&vtlo, g_vtlo);
    cudaGetSymbolAddress((void**)&s,    g_s);
    cudaGetSymbolAddress((void**)&elo,  g_elo);
    cudaGetSymbolAddress((void**)&o,    g_o);
    cudaGetSymbolAddress((void**)&cm,   g_cm);
    cudaGetSymbolAddress((void**)&pt,   g_pt);
    cudaGetSymbolAddress((void**)&ic,   g_ic);

    cudaFuncSetAttribute(gemm2, cudaFuncAttributeMaxDynamicSharedMemorySize, GSMEM);

    dim3 blk(256);
    dim3 gHid(NHID / NT, NROWS / MT);    // (4, 64)
    dim3 gScr(NROWS / NT, NROWS / MT);   // (32, 64)

    // input splits
    split2<<<(NROWS * NSPIN) / 1024, blk>>>(x, xhi, xlo);
    split2<<<(NHID * NSPIN) / 1024, blk>>>(Win, wihi, wilo);
    split2<<<(NHID * NHID) / 1024, blk>>>(Wq, wqhi, wqlo);
    split2<<<(NHID * NHID) / 1024, blk>>>(Wk, wkhi, wklo);
    split2<<<(NHID * NHID) / 1024, blk>>>(Wv, wvhi, wvlo);

    // h = x @ Win^T + b (split out)
    gemm2<<<gHid, blk, GSMEM>>>(xhi, xlo, wihi, wilo, bin, nullptr, hhi, hlo,
                                NROWS, NHID, NSPIN, 1.f);
    // q = 0.25 * h @ Wq^T (split out); k = h @ Wk^T (split out); v plain
    gemm2<<<gHid, blk, GSMEM>>>(hhi, hlo, wqhi, wqlo, nullptr, nullptr, qhi, qlo,
                                NROWS, NHID, NHID, 0.25f);
    gemm2<<<gHid, blk, GSMEM>>>(hhi, hlo, wkhi, wklo, nullptr, nullptr, khi, klo,
                                NROWS, NHID, NHID, 1.f);
    gemm2<<<gHid, blk, GSMEM>>>(hhi, hlo, wvhi, wvlo, nullptr, v, nullptr, nullptr,
                                NROWS, NHID, NHID, 1.f);
    // scores = q @ k^T (plain)
    gemm2<<<gScr, blk, GSMEM>>>(qhi, qlo, khi, klo, nullptr, s, nullptr, nullptr,
                                NROWS, NROWS, NHID, 1.f);
    // column softmax -> E (split, in place) + 1/colsum
    colmax_part<<<dim3(NROWS / 256, 64), blk>>>(s, pt);
    colmax_fin <<<NROWS / 256, blk>>>(pt, cm);
    expsum_part<<<dim3(NROWS / 256, 64), blk>>>(s, elo, cm, pt);
    invsum_fin <<<NROWS / 256, blk>>>(pt, ic);
    // vt = (v / colsum)^T (split)
    transpose_scale2<<<dim3(NHID / 32, NROWS / 32), dim3(32, 8)>>>(v, ic, vthi, vtlo);
    // o = E @ vt^T (plain)
    gemm2<<<gHid, blk, GSMEM>>>(s, elo, vthi, vtlo, nullptr, o, nullptr, nullptr,
                                NROWS, NHID, NROWS, 1.f);
    // per-row logcosh sum
    logcosh_rows<<<NROWS, blk>>>(o, out);
}

// round 5
// speedup vs baseline: 7.2387x; 1.5237x over previous
#include <cuda_runtime.h>
#include <cuda_fp16.h>
#include <cstdint>

#define NROWS 8192
#define NSPIN 1024
#define NHID  1024
#define KC    32
#define MT    128
#define NT    256

// ------------------------ scratch (device globals) ------------------------
__device__ float g_xhi[(size_t)NROWS * NSPIN];
__device__ float g_xlo[(size_t)NROWS * NSPIN];
__device__ float g_wihi[(size_t)NHID * NSPIN];
__device__ float g_wilo[(size_t)NHID * NSPIN];
__device__ float g_wqhi[(size_t)NHID * NHID];
__device__ float g_wqlo[(size_t)NHID * NHID];
__device__ float g_wkhi[(size_t)NHID * NHID];
__device__ float g_wklo[(size_t)NHID * NHID];
__device__ float g_wvhi[(size_t)NHID * NHID];
__device__ float g_wvlo[(size_t)NHID * NHID];
__device__ float g_hhi[(size_t)NROWS * NHID];
__device__ float g_hlo[(size_t)NROWS * NHID];
__device__ float g_qhi[(size_t)NROWS * NHID];
__device__ float g_qlo[(size_t)NROWS * NHID];
__device__ float g_khi[(size_t)NROWS * NHID];
__device__ float g_klo[(size_t)NROWS * NHID];
__device__ float g_v  [(size_t)NROWS * NHID];
__device__ __half g_vth[(size_t)NHID * NROWS];   // (v * 4096/c)^T, fp16
__device__ float g_s  [(size_t)NROWS * NROWS];   // scores (f32)
__device__ __half g_eh[(size_t)NROWS * NROWS];   // E' = 4096*exp(s-m), fp16
__device__ float g_o  [(size_t)NROWS * NHID];
__device__ float g_cm [NROWS];
__device__ float g_pt [(size_t)64 * NROWS];
__device__ float g_ic [NROWS];

// ------------------------ portable helpers ------------------------
__device__ __forceinline__ float tf32_rna(float x) {
    uint32_t u = __float_as_uint(x);
    u = (u + 0x1000u) & 0xFFFFE000u;
    return __uint_as_float(u);
}

#define SM103A_PATH (defined(__CUDA_ARCH__) && defined(__CUDA_ARCH_FEAT_SM103_ALL))

#if SM103A_PATH
__device__ __forceinline__ uint32_t smem_u32(const void* p) {
    uint32_t a;
    asm("{ .reg .u64 t; cvta.to.shared.u64 t, %1; cvt.u32.u64 %0, t; }"
        : "=r"(a) : "l"(p));
    return a;
}
__device__ __forceinline__ uint32_t elect_one() {
    uint32_t p;
    asm volatile("{\n\t.reg .pred p;\n\telect.sync _|p, 0xFFFFFFFF;\n\t"
                 "selp.b32 %0, 1, 0, p;\n\t}" : "=r"(p));
    return p;
}
__device__ __forceinline__ uint32_t swz128(uint32_t off) {
    return off ^ ((off >> 3) & 0x70);
}
__device__ __forceinline__ void mma_tf32(uint32_t d, uint64_t a, uint64_t b,
                                         uint32_t idesc, uint32_t en) {
    asm volatile("{\n\t.reg .pred p;\n\tsetp.ne.u32 p, %4, 0;\n\t"
                 "tcgen05.mma.cta_group::1.kind::tf32 [%0], %1, %2, %3, p;\n\t}"
                 :: "r"(d), "l"(a), "l"(b), "r"(idesc), "r"(en) : "memory");
}
__device__ __forceinline__ void mma_f16(uint32_t d, uint64_t a, uint64_t b,
                                        uint32_t idesc, uint32_t en) {
    asm volatile("{\n\t.reg .pred p;\n\tsetp.ne.u32 p, %4, 0;\n\t"
                 "tcgen05.mma.cta_group::1.kind::f16 [%0], %1, %2, %3, p;\n\t}"
                 :: "r"(d), "l"(a), "l"(b), "r"(idesc), "r"(en) : "memory");
}
__device__ __forceinline__ void cpa16(uint32_t dst, const void* src) {
    asm volatile("cp.async.cg.shared.global [%0], [%1], 16;"
                 :: "r"(dst), "l"(src) : "memory");
}
#define CP_COMMIT() asm volatile("cp.async.commit_group;" ::: "memory")
#define CP_WAIT0()  asm volatile("cp.async.wait_group 0;" ::: "memory")
#define TC_ALLOC(sa, n) \
    asm volatile("tcgen05.alloc.cta_group::1.sync.aligned.shared::cta.b32 [%0], %1;" \
                 :: "r"(sa), "r"(n) : "memory")
#define TC_RELINQ() \
    asm volatile("tcgen05.relinquish_alloc_permit.cta_group::1.sync.aligned;")
#define TC_DEALLOC(t, n) \
    asm volatile("tcgen05.dealloc.cta_group::1.sync.aligned.b32 %0, %1;" :: "r"(t), "r"(n))
#define TC_COMMIT(mb) \
    asm volatile("tcgen05.commit.cta_group::1.mbarrier::arrive::one.shared::cluster.b64 [%0];" \
                 :: "r"(mb) : "memory")
#define TC_FENCE_AFTER()  asm volatile("tcgen05.fence::after_thread_sync;" ::: "memory")
#define TC_WAIT_LD()      asm volatile("tcgen05.wait::ld.sync.aligned;" ::: "memory")
#define FENCE_ASYNC()     asm volatile("fence.proxy.async.shared::cta;" ::: "memory")
#define MBAR_INIT(mb, c) \
    asm volatile("mbarrier.init.shared.b64 [%0], %1;" :: "r"(mb), "r"(c) : "memory")
#define MBAR_WAIT(mb, par) do {                                                  \
    asm volatile("{\n\t.reg .pred P1;\n\t"                                       \
                 "WAIT_LOOP_%=:\n\t"                                             \
                 "mbarrier.try_wait.parity.acquire.cta.shared::cta.b64 P1, [%0], %1, 0x989680;\n\t" \
                 "@P1 bra.uni WAIT_DONE_%=;\n\t"                                 \
                 "bra.uni WAIT_LOOP_%=;\n\t"                                     \
                 "WAIT_DONE_%=:\n\t}"                                            \
                 :: "r"(mb), "r"(par) : "memory");                               \
} while (0)

__device__ __forceinline__ void ldtm32(uint32_t* r, uint32_t addr) {
    asm volatile(
        "tcgen05.ld.sync.aligned.32x32b.x32.b32 "
        "{%0, %1, %2, %3, %4, %5, %6, %7, "
        " %8, %9, %10, %11, %12, %13, %14, %15, "
        " %16, %17, %18, %19, %20, %21, %22, %23, "
        " %24, %25, %26, %27, %28, %29, %30, %31}, [%32];"
        : "=r"(r[0]),  "=r"(r[1]),  "=r"(r[2]),  "=r"(r[3]),
          "=r"(r[4]),  "=r"(r[5]),  "=r"(r[6]),  "=r"(r[7]),
          "=r"(r[8]),  "=r"(r[9]),  "=r"(r[10]), "=r"(r[11]),
          "=r"(r[12]), "=r"(r[13]), "=r"(r[14]), "=r"(r[15]),
          "=r"(r[16]), "=r"(r[17]), "=r"(r[18]), "=r"(r[19]),
          "=r"(r[20]), "=r"(r[21]), "=r"(r[22]), "=r"(r[23]),
          "=r"(r[24]), "=r"(r[25]), "=r"(r[26]), "=r"(r[27]),
          "=r"(r[28]), "=r"(r[29]), "=r"(r[30]), "=r"(r[31])
        : "r"(addr));
}
// SMEM descriptor: SW128, Blackwell version=1, LBO=1, SBO=64 (K-major)
__device__ __forceinline__ uint64_t smem_desc(uint32_t addr) {
    return ((uint64_t)2 << 61) | ((uint64_t)1 << 46) | ((uint64_t)64 << 32) |
           ((uint64_t)1 << 16) | ((uint64_t)(addr >> 4) & 0x3FFF);
}
// idesc: dtype=f32, N=256, M=128, K-major
#define IDESC_TF32 ((1u << 4) | (2u << 7) | (2u << 10) | (32u << 17) | (8u << 24))
#define IDESC_F16  ((1u << 4) | (32u << 17) | (8u << 24))
#endif  // SM103A_PATH

// SMEM layouts
#define SM_TMEMP  0
#define SM_MB     16
#define SM_TILES  1024
#define ABYTES    16384
#define BBYTES    32768
#define BUFB      (2 * ABYTES + 2 * BBYTES)
#define GSMEM     (SM_TILES + 2 * BUFB)        // 197632  (tf32, hi+lo)
#define FBUFB     (ABYTES + BBYTES)            // 49152   (fp16 single)
#define FSMEM     (SM_TILES + 2 * FBUFB)       // 99328

// ==========================================================================
// tf32 GEMM: C = alpha * A @ B^T (+bias). terms=3 -> 3xTF32; terms=1 -> hi only.
// ==========================================================================
__global__ void __launch_bounds__(256, 1)
gemm2(const float* __restrict__ Ahi, const float* __restrict__ Alo,
      const float* __restrict__ Bhi, const float* __restrict__ Blo,
      const float* __restrict__ bias, float* __restrict__ C,
      float* __restrict__ Chi, float* __restrict__ Clo,
      int M, int N, int K, float alpha, int terms) {
#if SM103A_PATH
    extern __shared__ char smem[];
    const uint32_t sb = smem_u32(smem);
    const int tid = threadIdx.x;
    const int wid = tid >> 5;
    const int lid = tid & 31;
    const int m0 = blockIdx.y * MT;
    const int n0 = blockIdx.x * NT;

    if (wid == 0) { TC_ALLOC(sb + SM_TMEMP, 256); TC_RELINQ(); }
    if (tid == 0) { MBAR_INIT(sb + SM_MB, 1); MBAR_INIT(sb + SM_MB + 8, 1); }
    __syncthreads();
    uint32_t tmem;
    asm volatile("ld.shared.b32 %0, [%1];" : "=r"(tmem) : "r"(sb + SM_TMEMP));

    uint32_t dA[4], dB[8];
    const float *pAh[4], *pAl[4], *pBh[8], *pBl[8];
    #pragma unroll
    for (int i = 0; i < 4; i++) {
        int idx = tid + 256 * i, r = idx >> 3, c = idx & 7;
        dA[i] = swz128((uint32_t)(r * 128 + c * 16));
        size_t go = (size_t)(m0 + r) * K + c * 4;
        pAh[i] = Ahi + go;  pAl[i] = Alo + go;
    }
    #pragma unroll
    for (int i = 0; i < 8; i++) {
        int idx = tid + 256 * i, r = idx >> 3, c = idx & 7;
        dB[i] = swz128((uint32_t)(r * 128 + c * 16));
        size_t go = (size_t)(n0 + r) * K + c * 4;
        pBh[i] = Bhi + go;  pBl[i] = Blo + go;
    }

    const int nk = K / KC;
    const bool full = (terms == 3);

    {   // prologue
        uint32_t bb = sb + SM_TILES;
        #pragma unroll
        for (int i = 0; i < 4; i++) {
            cpa16(bb + dA[i], pAh[i]);
            if (full) cpa16(bb + ABYTES + dA[i], pAl[i]);
        }
        #pragma unroll
        for (int i = 0; i < 8; i++) {
            cpa16(bb + 2 * ABYTES + dB[i], pBh[i]);
            if (full) cpa16(bb + 2 * ABYTES + BBYTES + dB[i], pBl[i]);
        }
        CP_COMMIT();
    }

    for (int k0 = 0; k0 < nk; k0++) {
        CP_WAIT0();
        FENCE_ASYNC();
        __syncthreads();

        if (wid == 0 && elect_one()) {
            const int buf = k0 & 1;
            uint32_t tb = sb + SM_TILES + buf * BUFB;
            uint64_t dAh = smem_desc(tb);
            uint64_t dAl = smem_desc(tb + ABYTES);
            uint64_t dBh = smem_desc(tb + 2 * ABYTES);
            uint64_t dBl = smem_desc(tb + 2 * ABYTES + BBYTES);
            #pragma unroll
            for (int s = 0; s < 4; s++)
                mma_tf32(tmem, dAh + 2 * s, dBh + 2 * s, IDESC_TF32,
                         (k0 > 0 || s > 0) ? 1u : 0u);
            if (full) {
                #pragma unroll
                for (int s = 0; s < 4; s++)
                    mma_tf32(tmem, dAh + 2 * s, dBl + 2 * s, IDESC_TF32, 1u);
                #pragma unroll
                for (int s = 0; s < 4; s++)
                    mma_tf32(tmem, dAl + 2 * s, dBh + 2 * s, IDESC_TF32, 1u);
            }
            TC_COMMIT(sb + SM_MB + 8 * buf);
        }

        if (k0 + 1 < nk) {
            if (k0 >= 1)
                MBAR_WAIT(sb + SM_MB + 8 * ((k0 - 1) & 1), ((k0 - 1) >> 1) & 1);
            uint32_t bb = sb + SM_TILES + ((k0 + 1) & 1) * BUFB;
            const int off = (k0 + 1) * KC;
            #pragma unroll
            for (int i = 0; i < 4; i++) {
                cpa16(bb + dA[i], pAh[i] + off);
                if (full) cpa16(bb + ABYTES + dA[i], pAl[i] + off);
            }
            #pragma unroll
            for (int i = 0; i < 8; i++) {
                cpa16(bb + 2 * ABYTES + dB[i], pBh[i] + off);
                if (full) cpa16(bb + 2 * ABYTES + BBYTES + dB[i], pBl[i] + off);
            }
        }
        CP_COMMIT();
    }

    {
        const int last = nk - 1;
        MBAR_WAIT(sb + SM_MB + 8 * (last & 1), (last >> 1) & 1);
    }
    TC_FENCE_AFTER();

    if (wid < 4) {
        const int r = m0 + wid * 32 + lid;
        #pragma unroll
        for (int g = 0; g < 8; g++) {
            uint32_t d[32];
            ldtm32(d, tmem + g * 32);
            TC_WAIT_LD();
            const int c0 = n0 + g * 32;
            float vals[32];
            #pragma unroll
            for (int j = 0; j < 32; j++) {
                float v = __uint_as_float(d[j]) * alpha;
                if (bias) v += bias[c0 + j];
                vals[j] = v;
            }
            if (C) {
                float* crow = C + (size_t)r * N + c0;
                #pragma unroll
                for (int j = 0; j < 8; j++)
                    *(float4*)(crow + 4 * j) = make_float4(
                        vals[4 * j], vals[4 * j + 1], vals[4 * j + 2], vals[4 * j + 3]);
            }
            if (Chi) {
                float* hrow = Chi + (size_t)r * N + c0;
                float* lrow = Clo + (size_t)r * N + c0;
                #pragma unroll
                for (int j = 0; j < 8; j++) {
                    float h0 = tf32_rna(vals[4 * j + 0]), h1 = tf32_rna(vals[4 * j + 1]);
                    float h2 = tf32_rna(vals[4 * j + 2]), h3 = tf32_rna(vals[4 * j + 3]);
                    *(float4*)(hrow + 4 * j) = make_float4(h0, h1, h2, h3);
                    *(float4*)(lrow + 4 * j) = make_float4(
                        tf32_rna(vals[4 * j + 0] - h0), tf32_rna(vals[4 * j + 1] - h1),
                        tf32_rna(vals[4 * j + 2] - h2), tf32_rna(vals[4 * j + 3] - h3));
                }
            }
        }
    }
    __syncthreads();
    if (wid == 0) TC_DEALLOC(tmem, 256);

#else  // fallback (compile-only)
    const int tid = threadIdx.x;
    const int m0 = blockIdx.y * MT, n0 = blockIdx.x * NT;
    int r = m0 + (tid & 127);
    int cb = n0 + (tid >> 7) * 128;
    for (int j = 0; j < 128; j++) {
        int c = cb + j;
        float acc = 0.f;
        for (int kk = 0; kk < K; kk++) {
            float a = Ahi[(size_t)r * K + kk] + (terms == 3 ? Alo[(size_t)r * K + kk] : 0.f);
            float b = Bhi[(size_t)c * K + kk] + (terms == 3 ? Blo[(size_t)c * K + kk] : 0.f);
            acc += a * b;
        }
        float v = acc * alpha + (bias ? bias[c] : 0.f);
        if (C) C[(size_t)r * N + c] = v;
        if (Chi) {
            float h = tf32_rna(v);
            Chi[(size_t)r * N + c] = h;
            Clo[(size_t)r * N + c] = tf32_rna(v - h);
        }
    }
#endif
}

// ==========================================================================
// fp16 GEMM: C[M,N] = alpha * A[M,K] @ B[N,K]^T, fp16 in / fp32 accum+out.
// K-chunk = 64 halves (128B). Grid (N/256, M/128), 256 threads.
// ==========================================================================
__global__ void __launch_bounds__(256, 1)
gemm_f16(const __half* __restrict__ A, const __half* __restrict__ B,
         float* __restrict__ C, int M, int N, int K, float alpha) {
#if SM103A_PATH
    extern __shared__ char smem[];
    const uint32_t sb = smem_u32(smem);
    const int tid = threadIdx.x;
    const int wid = tid >> 5;
    const int lid = tid & 31;
    const int m0 = blockIdx.y * MT;
    const int n0 = blockIdx.x * NT;

    if (wid == 0) { TC_ALLOC(sb + SM_TMEMP, 256); TC_RELINQ(); }
    if (tid == 0) { MBAR_INIT(sb + SM_MB, 1); MBAR_INIT(sb + SM_MB + 8, 1); }
    __syncthreads();
    uint32_t tmem;
    asm volatile("ld.shared.b32 %0, [%1];" : "=r"(tmem) : "r"(sb + SM_TMEMP));

    uint32_t dA[4], dB[8];
    const __half *pA[4], *pB[8];
    #pragma unroll
    for (int i = 0; i < 4; i++) {
        int idx = tid + 256 * i, r = idx >> 3, c = idx & 7;
        dA[i] = swz128((uint32_t)(r * 128 + c * 16));
        pA[i] = A + (size_t)(m0 + r) * K + c * 8;
    }
    #pragma unroll
    for (int i = 0; i < 8; i++) {
        int idx = tid + 256 * i, r = idx >> 3, c = idx & 7;
        dB[i] = swz128((uint32_t)(r * 128 + c * 16));
        pB[i] = B + (size_t)(n0 + r) * K + c * 8;
    }

    const int nk = K / 64;

    {   // prologue
        uint32_t bb = sb + SM_TILES;
        #pragma unroll
        for (int i = 0; i < 4; i++) cpa16(bb + dA[i], pA[i]);
        #pragma unroll
        for (int i = 0; i < 8; i++) cpa16(bb + ABYTES + dB[i], pB[i]);
        CP_COMMIT();
    }

    for (int k0 = 0; k0 < nk; k0++) {
        CP_WAIT0();
        FENCE_ASYNC();
        __syncthreads();

        if (wid == 0 && elect_one()) {
            const int buf = k0 & 1;
            uint32_t tb = sb + SM_TILES + buf * FBUFB;
            uint64_t dAd = smem_desc(tb);
            uint64_t dBd = smem_desc(tb + ABYTES);
            #pragma unroll
            for (int s = 0; s < 4; s++)
                mma_f16(tmem, dAd + 2 * s, dBd + 2 * s, IDESC_F16,
                        (k0 > 0 || s > 0) ? 1u : 0u);
            TC_COMMIT(sb + SM_MB + 8 * buf);
        }

        if (k0 + 1 < nk) {
            if (k0 >= 1)
                MBAR_WAIT(sb + SM_MB + 8 * ((k0 - 1) & 1), ((k0 - 1) >> 1) & 1);
            uint32_t bb = sb + SM_TILES + ((k0 + 1) & 1) * FBUFB;
            const int off = (k0 + 1) * 64;
            #pragma unroll
            for (int i = 0; i < 4; i++) cpa16(bb + dA[i], pA[i] + off);
            #pragma unroll
            for (int i = 0; i < 8; i++) cpa16(bb + ABYTES + dB[i], pB[i] + off);
        }
        CP_COMMIT();
    }

    {
        const int last = nk - 1;
        MBAR_WAIT(sb + SM_MB + 8 * (last & 1), (last >> 1) & 1);
    }
    TC_FENCE_AFTER();

    if (wid < 4) {
        const int r = m0 + wid * 32 + lid;
        #pragma unroll
        for (int g = 0; g < 8; g++) {
            uint32_t d[32];
            ldtm32(d, tmem + g * 32);
            TC_WAIT_LD();
            float* crow = C + (size_t)r * N + n0 + g * 32;
            #pragma unroll
            for (int j = 0; j < 8; j++)
                *(float4*)(crow + 4 * j) = make_float4(
                    __uint_as_float(d[4 * j + 0]) * alpha,
                    __uint_as_float(d[4 * j + 1]) * alpha,
                    __uint_as_float(d[4 * j + 2]) * alpha,
                    __uint_as_float(d[4 * j + 3]) * alpha);
        }
    }
    __syncthreads();
    if (wid == 0) TC_DEALLOC(tmem, 256);

#else  // fallback (compile-only)
    const int tid = threadIdx.x;
    const int m0 = blockIdx.y * MT, n0 = blockIdx.x * NT;
    int r = m0 + (tid & 127);
    int cb = n0 + (tid >> 7) * 128;
    for (int j = 0; j < 128; j++) {
        int c = cb + j;
        float acc = 0.f;
        for (int kk = 0; kk < K; kk++)
            acc += __half2float(A[(size_t)r * K + kk]) *
                   __half2float(B[(size_t)c * K + kk]);
        C[(size_t)r * N + c] = acc * alpha;
    }
#endif
}

// ==========================================================================
// elementwise split
// ==========================================================================
__global__ void split2(const float* __restrict__ in, float* __restrict__ hi,
                       float* __restrict__ lo) {
    size_t i = ((size_t)blockIdx.x * 256 + threadIdx.x) * 4;
    float4 v = *(const float4*)(in + i);
    float4 h, l;
    h.x = tf32_rna(v.x); l.x = tf32_rna(v.x - h.x);
    h.y = tf32_rna(v.y); l.y = tf32_rna(v.y - h.y);
    h.z = tf32_rna(v.z); l.z = tf32_rna(v.z - h.z);
    h.w = tf32_rna(v.w); l.w = tf32_rna(v.w - h.w);
    *(float4*)(hi + i) = h;
    *(float4*)(lo + i) = l;
}

// ==========================================================================
// Column softmax (axis 0)
// ==========================================================================
#define ROWS_PER_BLK 128

__global__ void colmax_part(const float* __restrict__ S, float* __restrict__ part) {
    int j = blockIdx.x * 256 + threadIdx.x;
    int r0 = blockIdx.y * ROWS_PER_BLK;
    const float* p = S + (size_t)r0 * NROWS + j;
    float m = -3.402823e38f;
    #pragma unroll 8
    for (int i = 0; i < ROWS_PER_BLK; i++)
        m = fmaxf(m, p[(size_t)i * NROWS]);
    part[(size_t)blockIdx.y * NROWS + j] = m;
}

__global__ void colmax_fin(const float* __restrict__ part, float* __restrict__ cm) {
    int j = blockIdx.x * 256 + threadIdx.x;
    float m = -3.402823e38f;
    #pragma unroll
    for (int i = 0; i < 64; i++)
        m = fmaxf(m, part[(size_t)i * NROWS + j]);
    cm[j] = m;
}

// E' = 2^12 * exp(s - m)  via ex2.approx.f16x2; partial column sums of E'
__global__ void expsum_half(const float* __restrict__ S, __half* __restrict__ E,
                            const float* __restrict__ cm, float* __restrict__ part) {
    int j = blockIdx.x * 256 + threadIdx.x;
    int r0 = blockIdx.y * ROWS_PER_BLK;
    const float* p = S + (size_t)r0 * NROWS + j;
    __half* pe = E + (size_t)r0 * NROWS + j;
    float mj = cm[j];
    const float L2E = 1.4426950408889634f;
    float c = 0.f;
    #pragma unroll 4
    for (int i = 0; i < ROWS_PER_BLK; i += 2) {
        float t0 = (p[(size_t)i * NROWS] - mj) * L2E + 12.f;
        float t1 = (p[(size_t)(i + 1) * NROWS] - mj) * L2E + 12.f;
        __half2 he = h2exp2(__floats2half2_rn(t0, t1));
        pe[(size_t)i * NROWS] = __low2half(he);
        pe[(size_t)(i + 1) * NROWS] = __high2half(he);
        float2 f = __half22float2(he);
        c += f.x + f.y;
    }
    part[(size_t)blockIdx.y * NROWS + j] = c;
}

__global__ void invsum_fin(const float* __restrict__ part, float* __restrict__ ic) {
    int j = blockIdx.x * 256 + threadIdx.x;
    float c = 0.f;
    #pragma unroll
    for (int i = 0; i < 64; i++)
        c += part[(size_t)i * NROWS + j];
    ic[j] = 1.f / c;
}

// ==========================================================================
// vth[n,k] = fp16( v[k,n] * 4096 * ic[k] )   (attnV alpha folds 1/4096)
// ==========================================================================
__global__ void transpose_scale_h(const float* __restrict__ V,
                                  const float* __restrict__ ic,
                                  __half* __restrict__ VT) {
    __shared__ float t[32][33];
    int n = blockIdx.x * 32 + threadIdx.x;
    int k = blockIdx.y * 32 + threadIdx.y;
    #pragma unroll
    for (int i = 0; i < 32; i += 8)
        t[threadIdx.y + i][threadIdx.x] =
            V[(size_t)(k + i) * NHID + n] * (4096.f * ic[k + i]);
    __syncthreads();
    int ko = blockIdx.y * 32 + threadIdx.x;
    int no = blockIdx.x * 32 + threadIdx.y;
    #pragma unroll
    for (int i = 0; i < 32; i += 8)
        VT[(size_t)(no + i) * NROWS + ko] = __float2half(t[threadIdx.x][threadIdx.y + i]);
}

// ==========================================================================
// out[i] = sum_h logcosh(O[i,h]) ; exp via f16x2 MUFU, log1p via lg2 MUFU
// ==========================================================================
__global__ void logcosh_rows(const float* __restrict__ O, float* __restrict__ out) {
    __shared__ float red[256];
    int row = blockIdx.x;
    const float* o = O + (size_t)row * NHID;
    int t = threadIdx.x;
    float a0 = fabsf(o[t]);
    float a1 = fabsf(o[t + 256]);
    float a2 = fabsf(o[t + 512]);
    float a3 = fabsf(o[t + 768]);
    const float N2L2E = -2.f * 1.4426950408889634f;
    __half2 w01 = h2exp2(__floats2half2_rn(a0 * N2L2E, a1 * N2L2E));
    __half2 w23 = h2exp2(__floats2half2_rn(a2 * N2L2E, a3 * N2L2E));
    float2 f01 = __half22float2(w01), f23 = __half22float2(w23);
    const float LN2 = 0.69314718055994531f;
    float s = a0 + a1 + a2 + a3 +
              LN2 * (__log2f(1.f + f01.x) + __log2f(1.f + f01.y) +
                     __log2f(1.f + f23.x) + __log2f(1.f + f23.y));
    red[t] = s;
    __syncthreads();
    for (int st = 128; st > 0; st >>= 1) {
        if (t < st) red[t] += red[t + st];
        __syncthreads();
    }
    if (t == 0)
        out[row] = red[0] - (float)NHID * LN2;
}

// ==========================================================================
extern "C" void kernel_launch(void* const* d_in, const int* in_sizes, int n_in,
                              void* d_out, int out_size) {
    const float* x   = (const float*)d_in[0];
    const float* Win = (const float*)d_in[1];
    const float* bin = (const float*)d_in[2];
    const float* Wq  = (const float*)d_in[3];
    const float* Wk  = (const float*)d_in[4];
    const float* Wv  = (const float*)d_in[5];
    float* out = (float*)d_out;

    float *xhi, *xlo, *wihi, *wilo, *wqhi, *wqlo, *wkhi, *wklo, *wvhi, *wvlo;
    float *hhi, *hlo, *qhi, *qlo, *khi, *klo, *v;
    float *s, *o, *cm, *pt, *ic;
    __half *eh, *vth;
    cudaGetSymbolAddress((void**)&xhi,  g_xhi);
    cudaGetSymbolAddress((void**)&xlo,  g_xlo);
    cudaGetSymbolAddress((void**)&wihi, g_wihi);
    cudaGetSymbolAddress((void**)&wilo, g_wilo);
    cudaGetSymbolAddress((void**)&wqhi, g_wqhi);
    cudaGetSymbolAddress((void**)&wqlo, g_wqlo);
    cudaGetSymbolAddress((void**)&wkhi, g_wkhi);
    cudaGetSymbolAddress((void**)&wklo, g_wklo);
    cudaGetSymbolAddress((void**)&wvhi, g_wvhi);
    cudaGetSymbolAddress((void**)&wvlo, g_wvlo);
    cudaGetSymbolAddress((void**)&hhi,  g_hhi);
    cudaGetSymbolAddress((void**)&hlo,  g_hlo);
    cudaGetSymbolAddress((void**)&qhi,  g_qhi);
    cudaGetSymbolAddress((void**)&qlo,  g_qlo);
    cudaGetSymbolAddress((void**)&khi,  g_khi);
    cudaGetSymbolAddress((void**)&klo,  g_klo);
    cudaGetSymbolAddress((void**)&v,    g_v);
    cudaGetSymbolAddress((void**)&vth,  g_vth);
    cudaGetSymbolAddress((void**)&s,    g_s);
    cudaGetSymbolAddress((void**)&eh,   g_eh);
    cudaGetSymbolAddress((void**)&o,    g_o);
    cudaGetSymbolAddress((void**)&cm,   g_cm);
    cudaGetSymbolAddress((void**)&pt,   g_pt);
    cudaGetSymbolAddress((void**)&ic,   g_ic);

    cudaFuncSetAttribute(gemm2, cudaFuncAttributeMaxDynamicSharedMemorySize, GSMEM);
    cudaFuncSetAttribute(gemm_f16, cudaFuncAttributeMaxDynamicSharedMemorySize, FSMEM);

    dim3 blk(256);
    dim3 gHid(NHID / NT, NROWS / MT);    // (4, 64)
    dim3 gScr(NROWS / NT, NROWS / MT);   // (32, 64)

    // input splits
    split2<<<(NROWS * NSPIN) / 1024, blk>>>(x, xhi, xlo);
    split2<<<(NHID * NSPIN) / 1024, blk>>>(Win, wihi, wilo);
    split2<<<(NHID * NHID) / 1024, blk>>>(Wq, wqhi, wqlo);
    split2<<<(NHID * NHID) / 1024, blk>>>(Wk, wkhi, wklo);
    split2<<<(NHID * NHID) / 1024, blk>>>(Wv, wvhi, wvlo);

    // h = x @ Win^T + b (3-term, split out)
    gemm2<<<gHid, blk, GSMEM>>>(xhi, xlo, wihi, wilo, bin, nullptr, hhi, hlo,
                                NROWS, NHID, NSPIN, 1.f, 3);
    // q = 0.25 * h @ Wq^T ; k = h @ Wk^T (3-term, split out)
    gemm2<<<gHid, blk, GSMEM>>>(hhi, hlo, wqhi, wqlo, nullptr, nullptr, qhi, qlo,
                                NROWS, NHID, NHID, 0.25f, 3);
    gemm2<<<gHid, blk, GSMEM>>>(hhi, hlo, wkhi, wklo, nullptr, nullptr, khi, klo,
                                NROWS, NHID, NHID, 1.f, 3);
    // v = h @ Wv^T (1-term tf32, plain out)
    gemm2<<<gHid, blk, GSMEM>>>(hhi, hlo, wvhi, wvlo, nullptr, v, nullptr, nullptr,
                                NROWS, NHID, NHID, 1.f, 1);
    // scores = q @ k^T (3-term, plain out)
    gemm2<<<gScr, blk, GSMEM>>>(qhi, qlo, khi, klo, nullptr, s, nullptr, nullptr,
                                NROWS, NROWS, NHID, 1.f, 3);
    // column softmax -> E' fp16 + 1/colsum
    colmax_part<<<dim3(NROWS / 256, 64), blk>>>(s, pt);
    colmax_fin <<<NROWS / 256, blk>>>(pt, cm);
    expsum_half<<<dim3(NROWS / 256, 64), blk>>>(s, eh, cm, pt);
    invsum_fin <<<NROWS / 256, blk>>>(pt, ic);
    // vth = fp16((v * 4096/c)^T)
    transpose_scale_h<<<dim3(NHID / 32, NROWS / 32), dim3(32, 8)>>>(v, ic, vth);
    // o = (1/4096) * E' @ vth^T   (fp16 MMA)
    gemm_f16<<<gHid, blk, FSMEM>>>(eh, vth, o, NROWS, NHID, NROWS, 1.f / 4096.f);
    // per-row logcosh sum
    logcosh_rows<<<NROWS, blk>>>(o, out);
}

// round 6
// speedup vs baseline: 9.7942x; 1.3530x over previous
#include <cuda_runtime.h>
#include <cuda_fp16.h>
#include <cstdint>

#define NROWS 8192
#define NSPIN 1024
#define NHID  1024
#define MT    128
#define NT    256

// ------------------------ scratch (device globals) ------------------------
__device__ __half g_xhi[(size_t)NROWS * NSPIN];
__device__ __half g_xlo[(size_t)NROWS * NSPIN];
__device__ __half g_wihi[(size_t)NHID * NSPIN];
__device__ __half g_wilo[(size_t)NHID * NSPIN];
__device__ __half g_wqhi[(size_t)NHID * NHID];
__device__ __half g_wqlo[(size_t)NHID * NHID];
__device__ __half g_wkhi[(size_t)NHID * NHID];
__device__ __half g_wklo[(size_t)NHID * NHID];
__device__ __half g_wvhi[(size_t)NHID * NHID];
__device__ __half g_wvlo[(size_t)NHID * NHID];
__device__ __half g_hhi[(size_t)NROWS * NHID];
__device__ __half g_hlo[(size_t)NROWS * NHID];
__device__ __half g_qhi[(size_t)NROWS * NHID];
__device__ __half g_qlo[(size_t)NROWS * NHID];
__device__ __half g_khi[(size_t)NROWS * NHID];
__device__ __half g_klo[(size_t)NROWS * NHID];
__device__ float  g_v  [(size_t)NROWS * NHID];
__device__ __half g_vth[(size_t)NHID * NROWS];   // (v * 4096/c)^T
__device__ float  g_s  [(size_t)NROWS * NROWS];  // scores f32
__device__ __half g_eh [(size_t)NROWS * NROWS];  // E' = 4096*exp(s-m)
__device__ float  g_o  [(size_t)NROWS * NHID];
__device__ float  g_cm [NROWS];
__device__ float  g_pt [(size_t)64 * NROWS];
__device__ float  g_ic [NROWS];

#define SM103A_PATH (defined(__CUDA_ARCH__) && defined(__CUDA_ARCH_FEAT_SM103_ALL))

#if SM103A_PATH
__device__ __forceinline__ uint32_t smem_u32(const void* p) {
    uint32_t a;
    asm("{ .reg .u64 t; cvta.to.shared.u64 t, %1; cvt.u32.u64 %0, t; }"
        : "=r"(a) : "l"(p));
    return a;
}
__device__ __forceinline__ uint32_t elect_one() {
    uint32_t p;
    asm volatile("{\n\t.reg .pred p;\n\telect.sync _|p, 0xFFFFFFFF;\n\t"
                 "selp.b32 %0, 1, 0, p;\n\t}" : "=r"(p));
    return p;
}
__device__ __forceinline__ uint32_t swz128(uint32_t off) {
    return off ^ ((off >> 3) & 0x70);
}
__device__ __forceinline__ void mma_f16(uint32_t d, uint64_t a, uint64_t b,
                                        uint32_t idesc, uint32_t en) {
    asm volatile("{\n\t.reg .pred p;\n\tsetp.ne.u32 p, %4, 0;\n\t"
                 "tcgen05.mma.cta_group::1.kind::f16 [%0], %1, %2, %3, p;\n\t}"
                 :: "r"(d), "l"(a), "l"(b), "r"(idesc), "r"(en) : "memory");
}
__device__ __forceinline__ void cpa16(uint32_t dst, const void* src) {
    asm volatile("cp.async.cg.shared.global [%0], [%1], 16;"
                 :: "r"(dst), "l"(src) : "memory");
}
#define CP_COMMIT() asm volatile("cp.async.commit_group;" ::: "memory")
#define CP_WAIT0()  asm volatile("cp.async.wait_group 0;" ::: "memory")
#define TC_ALLOC(sa, n) \
    asm volatile("tcgen05.alloc.cta_group::1.sync.aligned.shared::cta.b32 [%0], %1;" \
                 :: "r"(sa), "r"(n) : "memory")
#define TC_RELINQ() \
    asm volatile("tcgen05.relinquish_alloc_permit.cta_group::1.sync.aligned;")
#define TC_DEALLOC(t, n) \
    asm volatile("tcgen05.dealloc.cta_group::1.sync.aligned.b32 %0, %1;" :: "r"(t), "r"(n))
#define TC_COMMIT(mb) \
    asm volatile("tcgen05.commit.cta_group::1.mbarrier::arrive::one.shared::cluster.b64 [%0];" \
                 :: "r"(mb) : "memory")
#define TC_FENCE_AFTER()  asm volatile("tcgen05.fence::after_thread_sync;" ::: "memory")
#define TC_WAIT_LD()      asm volatile("tcgen05.wait::ld.sync.aligned;" ::: "memory")
#define FENCE_ASYNC()     asm volatile("fence.proxy.async.shared::cta;" ::: "memory")
#define MBAR_INIT(mb, c) \
    asm volatile("mbarrier.init.shared.b64 [%0], %1;" :: "r"(mb), "r"(c) : "memory")
#define MBAR_WAIT(mb, par) do {                                                  \
    asm volatile("{\n\t.reg .pred P1;\n\t"                                       \
                 "WAIT_LOOP_%=:\n\t"                                             \
                 "mbarrier.try_wait.parity.acquire.cta.shared::cta.b64 P1, [%0], %1, 0x989680;\n\t" \
                 "@P1 bra.uni WAIT_DONE_%=;\n\t"                                 \
                 "bra.uni WAIT_LOOP_%=;\n\t"                                     \
                 "WAIT_DONE_%=:\n\t}"                                            \
                 :: "r"(mb), "r"(par) : "memory");                               \
} while (0)

__device__ __forceinline__ void ldtm32(uint32_t* r, uint32_t addr) {
    asm volatile(
        "tcgen05.ld.sync.aligned.32x32b.x32.b32 "
        "{%0, %1, %2, %3, %4, %5, %6, %7, "
        " %8, %9, %10, %11, %12, %13, %14, %15, "
        " %16, %17, %18, %19, %20, %21, %22, %23, "
        " %24, %25, %26, %27, %28, %29, %30, %31}, [%32];"
        : "=r"(r[0]),  "=r"(r[1]),  "=r"(r[2]),  "=r"(r[3]),
          "=r"(r[4]),  "=r"(r[5]),  "=r"(r[6]),  "=r"(r[7]),
          "=r"(r[8]),  "=r"(r[9]),  "=r"(r[10]), "=r"(r[11]),
          "=r"(r[12]), "=r"(r[13]), "=r"(r[14]), "=r"(r[15]),
          "=r"(r[16]), "=r"(r[17]), "=r"(r[18]), "=r"(r[19]),
          "=r"(r[20]), "=r"(r[21]), "=r"(r[22]), "=r"(r[23]),
          "=r"(r[24]), "=r"(r[25]), "=r"(r[26]), "=r"(r[27]),
          "=r"(r[28]), "=r"(r[29]), "=r"(r[30]), "=r"(r[31])
        : "r"(addr));
}
// SMEM descriptor: SW128, Blackwell version=1, LBO=1, SBO=64 (K-major)
__device__ __forceinline__ uint64_t smem_desc(uint32_t addr) {
    return ((uint64_t)2 << 61) | ((uint64_t)1 << 46) | ((uint64_t)64 << 32) |
           ((uint64_t)1 << 16) | ((uint64_t)(addr >> 4) & 0x3FFF);
}
// idesc: dtype=f32, a=b=fp16, N=256, M=128, K-major
#define IDESC_F16  ((1u << 4) | (32u << 17) | (8u << 24))
#endif  // SM103A_PATH

// SMEM layout: per buffer [Ahi 16K][Alo 16K][Bhi 32K][Blo 32K]
#define SM_TMEMP  0
#define SM_MB     16
#define SM_TILES  1024
#define ABYTES    16384
#define BBYTES    32768
#define BUFB      (2 * ABYTES + 2 * BBYTES)
#define GSMEM     (SM_TILES + 2 * BUFB)      // 197632

// ==========================================================================
// fp16 3-term GEMM: C = alpha * A @ B^T (+bias), A,B fp16 hi/lo pairs.
// terms=3: hi*hi + hi*lo + lo*hi. terms=1: hi*hi only (Alo/Blo unused).
// Outputs: plain f32 C and/or fp16 split Chi/Clo.
// Grid (N/256, M/128), 256 threads. K % 64 == 0.
// ==========================================================================
__global__ void __launch_bounds__(256, 1)
gemm_h(const __half* __restrict__ Ahi, const __half* __restrict__ Alo,
       const __half* __restrict__ Bhi, const __half* __restrict__ Blo,
       const float* __restrict__ bias, float* __restrict__ C,
       __half* __restrict__ Chi, __half* __restrict__ Clo,
       int M, int N, int K, float alpha, int terms) {
#if SM103A_PATH
    extern __shared__ char smem[];
    const uint32_t sb = smem_u32(smem);
    const int tid = threadIdx.x;
    const int wid = tid >> 5;
    const int lid = tid & 31;
    const int m0 = blockIdx.y * MT;
    const int n0 = blockIdx.x * NT;

    if (wid == 0) { TC_ALLOC(sb + SM_TMEMP, 256); TC_RELINQ(); }
    if (tid == 0) { MBAR_INIT(sb + SM_MB, 1); MBAR_INIT(sb + SM_MB + 8, 1); }
    __syncthreads();
    uint32_t tmem;
    asm volatile("ld.shared.b32 %0, [%1];" : "=r"(tmem) : "r"(sb + SM_TMEMP));

    uint32_t dA[4], dB[8];
    const __half *pAh[4], *pAl[4], *pBh[8], *pBl[8];
    #pragma unroll
    for (int i = 0; i < 4; i++) {
        int idx = tid + 256 * i, r = idx >> 3, c = idx & 7;
        dA[i] = swz128((uint32_t)(r * 128 + c * 16));
        size_t go = (size_t)(m0 + r) * K + c * 8;
        pAh[i] = Ahi + go;  pAl[i] = Alo ? Alo + go : nullptr;
    }
    #pragma unroll
    for (int i = 0; i < 8; i++) {
        int idx = tid + 256 * i, r = idx >> 3, c = idx & 7;
        dB[i] = swz128((uint32_t)(r * 128 + c * 16));
        size_t go = (size_t)(n0 + r) * K + c * 8;
        pBh[i] = Bhi + go;  pBl[i] = Blo ? Blo + go : nullptr;
    }

    const int nk = K / 64;
    const bool full = (terms == 3);

    {   // prologue: stage 0
        uint32_t bb = sb + SM_TILES;
        #pragma unroll
        for (int i = 0; i < 4; i++) {
            cpa16(bb + dA[i], pAh[i]);
            if (full) cpa16(bb + ABYTES + dA[i], pAl[i]);
        }
        #pragma unroll
        for (int i = 0; i < 8; i++) {
            cpa16(bb + 2 * ABYTES + dB[i], pBh[i]);
            if (full) cpa16(bb + 2 * ABYTES + BBYTES + dB[i], pBl[i]);
        }
        CP_COMMIT();
    }

    for (int k0 = 0; k0 < nk; k0++) {
        CP_WAIT0();
        FENCE_ASYNC();
        __syncthreads();

        if (wid == 0 && elect_one()) {
            const int buf = k0 & 1;
            uint32_t tb = sb + SM_TILES + buf * BUFB;
            uint64_t dAh = smem_desc(tb);
            uint64_t dAl = smem_desc(tb + ABYTES);
            uint64_t dBh = smem_desc(tb + 2 * ABYTES);
            uint64_t dBl = smem_desc(tb + 2 * ABYTES + BBYTES);
            #pragma unroll
            for (int s = 0; s < 4; s++)
                mma_f16(tmem, dAh + 2 * s, dBh + 2 * s, IDESC_F16,
                        (k0 > 0 || s > 0) ? 1u : 0u);
            if (full) {
                #pragma unroll
                for (int s = 0; s < 4; s++)
                    mma_f16(tmem, dAh + 2 * s, dBl + 2 * s, IDESC_F16, 1u);
                #pragma unroll
                for (int s = 0; s < 4; s++)
                    mma_f16(tmem, dAl + 2 * s, dBh + 2 * s, IDESC_F16, 1u);
            }
            TC_COMMIT(sb + SM_MB + 8 * buf);
        }

        if (k0 + 1 < nk) {
            if (k0 >= 1)
                MBAR_WAIT(sb + SM_MB + 8 * ((k0 - 1) & 1), ((k0 - 1) >> 1) & 1);
            uint32_t bb = sb + SM_TILES + ((k0 + 1) & 1) * BUFB;
            const int off = (k0 + 1) * 64;
            #pragma unroll
            for (int i = 0; i < 4; i++) {
                cpa16(bb + dA[i], pAh[i] + off);
                if (full) cpa16(bb + ABYTES + dA[i], pAl[i] + off);
            }
            #pragma unroll
            for (int i = 0; i < 8; i++) {
                cpa16(bb + 2 * ABYTES + dB[i], pBh[i] + off);
                if (full) cpa16(bb + 2 * ABYTES + BBYTES + dB[i], pBl[i] + off);
            }
        }
        CP_COMMIT();
    }

    {
        const int last = nk - 1;
        MBAR_WAIT(sb + SM_MB + 8 * (last & 1), (last >> 1) & 1);
    }
    TC_FENCE_AFTER();

    if (wid < 4) {
        const int r = m0 + wid * 32 + lid;
        #pragma unroll
        for (int g = 0; g < 8; g++) {
            uint32_t d[32];
            ldtm32(d, tmem + g * 32);
            TC_WAIT_LD();
            const int c0 = n0 + g * 32;
            float vals[32];
            #pragma unroll
            for (int j = 0; j < 32; j++) {
                float v = __uint_as_float(d[j]) * alpha;
                if (bias) v += bias[c0 + j];
                vals[j] = v;
            }
            if (C) {
                float* crow = C + (size_t)r * N + c0;
                #pragma unroll
                for (int j = 0; j < 8; j++)
                    *(float4*)(crow + 4 * j) = make_float4(
                        vals[4 * j], vals[4 * j + 1], vals[4 * j + 2], vals[4 * j + 3]);
            }
            if (Chi) {
                __half* hrow = Chi + (size_t)r * N + c0;
                __half* lrow = Clo + (size_t)r * N + c0;
                #pragma unroll
                for (int j = 0; j < 16; j++) {
                    float v0 = vals[2 * j], v1 = vals[2 * j + 1];
                    __half h0 = __float2half(v0), h1 = __float2half(v1);
                    __half l0 = __float2half(v0 - __half2float(h0));
                    __half l1 = __float2half(v1 - __half2float(h1));
                    *(__half2*)(hrow + 2 * j) = __halves2half2(h0, h1);
                    *(__half2*)(lrow + 2 * j) = __halves2half2(l0, l1);
                }
            }
        }
    }
    __syncthreads();
    if (wid == 0) TC_DEALLOC(tmem, 256);

#else  // fallback (compile-only for plain compute_103 pass)
    const int tid = threadIdx.x;
    const int m0 = blockIdx.y * MT, n0 = blockIdx.x * NT;
    int r = m0 + (tid & 127);
    int cb = n0 + (tid >> 7) * 128;
    for (int j = 0; j < 128; j++) {
        int c = cb + j;
        float acc = 0.f;
        for (int kk = 0; kk < K; kk++) {
            float a = __half2float(Ahi[(size_t)r * K + kk]) +
                      (terms == 3 ? __half2float(Alo[(size_t)r * K + kk]) : 0.f);
            float b = __half2float(Bhi[(size_t)c * K + kk]) +
                      (terms == 3 ? __half2float(Blo[(size_t)c * K + kk]) : 0.f);
            acc += a * b;
        }
        float v = acc * alpha + (bias ? bias[c] : 0.f);
        if (C) C[(size_t)r * N + c] = v;
        if (Chi) {
            __half h = __float2half(v);
            Chi[(size_t)r * N + c] = h;
            Clo[(size_t)r * N + c] = __float2half(v - __half2float(h));
        }
    }
#endif
}

// ==========================================================================
// elementwise split f32 -> fp16 hi/lo
// ==========================================================================
__global__ void split2h(const float* __restrict__ in, __half* __restrict__ hi,
                        __half* __restrict__ lo) {
    size_t i = ((size_t)blockIdx.x * 256 + threadIdx.x) * 4;
    float4 v = *(const float4*)(in + i);
    __half h0 = __float2half(v.x), h1 = __float2half(v.y);
    __half h2 = __float2half(v.z), h3 = __float2half(v.w);
    __half2 hh0 = __halves2half2(h0, h1), hh1 = __halves2half2(h2, h3);
    __half2 ll0 = __halves2half2(__float2half(v.x - __half2float(h0)),
                                 __float2half(v.y - __half2float(h1)));
    __half2 ll1 = __halves2half2(__float2half(v.z - __half2float(h2)),
                                 __float2half(v.w - __half2float(h3)));
    *(__half2*)(hi + i) = hh0;
    *(__half2*)(hi + i + 2) = hh1;
    *(__half2*)(lo + i) = ll0;
    *(__half2*)(lo + i + 2) = ll1;
}

// ==========================================================================
// Column softmax (axis 0)
// ==========================================================================
#define ROWS_PER_BLK 128

__global__ void colmax_part(const float* __restrict__ S, float* __restrict__ part) {
    int j = blockIdx.x * 256 + threadIdx.x;
    int r0 = blockIdx.y * ROWS_PER_BLK;
    const float* p = S + (size_t)r0 * NROWS + j;
    float m = -3.402823e38f;
    #pragma unroll 8
    for (int i = 0; i < ROWS_PER_BLK; i++)
        m = fmaxf(m, p[(size_t)i * NROWS]);
    part[(size_t)blockIdx.y * NROWS + j] = m;
}

__global__ void colmax_fin(const float* __restrict__ part, float* __restrict__ cm) {
    int j = blockIdx.x * 256 + threadIdx.x;
    float m = -3.402823e38f;
    #pragma unroll
    for (int i = 0; i < 64; i++)
        m = fmaxf(m, part[(size_t)i * NROWS + j]);
    cm[j] = m;
}

// E' = 2^12 * exp(s - m) via ex2.approx.f16x2; partial column sums of E'
__global__ void expsum_half(const float* __restrict__ S, __half* __restrict__ E,
                            const float* __restrict__ cm, float* __restrict__ part) {
    int j = blockIdx.x * 256 + threadIdx.x;
    int r0 = blockIdx.y * ROWS_PER_BLK;
    const float* p = S + (size_t)r0 * NROWS + j;
    __half* pe = E + (size_t)r0 * NROWS + j;
    float mj = cm[j];
    const float L2E = 1.4426950408889634f;
    float c = 0.f;
    #pragma unroll 4
    for (int i = 0; i < ROWS_PER_BLK; i += 2) {
        float t0 = (p[(size_t)i * NROWS] - mj) * L2E + 12.f;
        float t1 = (p[(size_t)(i + 1) * NROWS] - mj) * L2E + 12.f;
        __half2 he = h2exp2(__floats2half2_rn(t0, t1));
        pe[(size_t)i * NROWS] = __low2half(he);
        pe[(size_t)(i + 1) * NROWS] = __high2half(he);
        float2 f = __half22float2(he);
        c += f.x + f.y;
    }
    part[(size_t)blockIdx.y * NROWS + j] = c;
}

__global__ void invsum_fin(const float* __restrict__ part, float* __restrict__ ic) {
    int j = blockIdx.x * 256 + threadIdx.x;
    float c = 0.f;
    #pragma unroll
    for (int i = 0; i < 64; i++)
        c += part[(size_t)i * NROWS + j];
    ic[j] = 1.f / c;
}

// ==========================================================================
// vth[n,k] = fp16( v[k,n] * 4096 * ic[k] )
// ==========================================================================
__global__ void transpose_scale_h(const float* __restrict__ V,
                                  const float* __restrict__ ic,
                                  __half* __restrict__ VT) {
    __shared__ float t[32][33];
    int n = blockIdx.x * 32 + threadIdx.x;
    int k = blockIdx.y * 32 + threadIdx.y;
    #pragma unroll
    for (int i = 0; i < 32; i += 8)
        t[threadIdx.y + i][threadIdx.x] =
            V[(size_t)(k + i) * NHID + n] * (4096.f * ic[k + i]);
    __syncthreads();
    int ko = blockIdx.y * 32 + threadIdx.x;
    int no = blockIdx.x * 32 + threadIdx.y;
    #pragma unroll
    for (int i = 0; i < 32; i += 8)
        VT[(size_t)(no + i) * NROWS + ko] = __float2half(t[threadIdx.x][threadIdx.y + i]);
}

// ==========================================================================
// out[i] = sum_h logcosh(O[i,h])
// ==========================================================================
__global__ void logcosh_rows(const float* __restrict__ O, float* __restrict__ out) {
    __shared__ float red[256];
    int row = blockIdx.x;
    const float* o = O + (size_t)row * NHID;
    int t = threadIdx.x;
    float a0 = fabsf(o[t]);
    float a1 = fabsf(o[t + 256]);
    float a2 = fabsf(o[t + 512]);
    float a3 = fabsf(o[t + 768]);
    const float N2L2E = -2.f * 1.4426950408889634f;
    __half2 w01 = h2exp2(__floats2half2_rn(a0 * N2L2E, a1 * N2L2E));
    __half2 w23 = h2exp2(__floats2half2_rn(a2 * N2L2E, a3 * N2L2E));
    float2 f01 = __half22float2(w01), f23 = __half22float2(w23);
    const float LN2 = 0.69314718055994531f;
    float s = a0 + a1 + a2 + a3 +
              LN2 * (__log2f(1.f + f01.x) + __log2f(1.f + f01.y) +
                     __log2f(1.f + f23.x) + __log2f(1.f + f23.y));
    red[t] = s;
    __syncthreads();
    for (int st = 128; st > 0; st >>= 1) {
        if (t < st) red[t] += red[t + st];
        __syncthreads();
    }
    if (t == 0)
        out[row] = red[0] - (float)NHID * LN2;
}

// ==========================================================================
extern "C" void kernel_launch(void* const* d_in, const int* in_sizes, int n_in,
                              void* d_out, int out_size) {
    const float* x   = (const float*)d_in[0];
    const float* Win = (const float*)d_in[1];
    const float* bin = (const float*)d_in[2];
    const float* Wq  = (const float*)d_in[3];
    const float* Wk  = (const float*)d_in[4];
    const float* Wv  = (const float*)d_in[5];
    float* out = (float*)d_out;

    __half *xhi, *xlo, *wihi, *wilo, *wqhi, *wqlo, *wkhi, *wklo, *wvhi, *wvlo;
    __half *hhi, *hlo, *qhi, *qlo, *khi, *klo, *vth, *eh;
    float *v, *s, *o, *cm, *pt, *ic;
    cudaGetSymbolAddress((void**)&xhi,  g_xhi);
    cudaGetSymbolAddress((void**)&xlo,  g_xlo);
    cudaGetSymbolAddress((void**)&wihi, g_wihi);
    cudaGetSymbolAddress((void**)&wilo, g_wilo);
    cudaGetSymbolAddress((void**)&wqhi, g_wqhi);
    cudaGetSymbolAddress((void**)&wqlo, g_wqlo);
    cudaGetSymbolAddress((void**)&wkhi, g_wkhi);
    cudaGetSymbolAddress((void**)&wklo, g_wklo);
    cudaGetSymbolAddress((void**)&wvhi, g_wvhi);
    cudaGetSymbolAddress((void**)&wvlo, g_wvlo);
    cudaGetSymbolAddress((void**)&hhi,  g_hhi);
    cudaGetSymbolAddress((void**)&hlo,  g_hlo);
    cudaGetSymbolAddress((void**)&qhi,  g_qhi);
    cudaGetSymbolAddress((void**)&qlo,  g_qlo);
    cudaGetSymbolAddress((void**)&khi,  g_khi);
    cudaGetSymbolAddress((void**)&klo,  g_klo);
    cudaGetSymbolAddress((void**)&v,    g_v);
    cudaGetSymbolAddress((void**)&vth,  g_vth);
    cudaGetSymbolAddress((void**)&s,    g_s);
    cudaGetSymbolAddress((void**)&eh,   g_eh);
    cudaGetSymbolAddress((void**)&o,    g_o);
    cudaGetSymbolAddress((void**)&cm,   g_cm);
    cudaGetSymbolAddress((void**)&pt,   g_pt);
    cudaGetSymbolAddress((void**)&ic,   g_ic);

    cudaFuncSetAttribute(gemm_h, cudaFuncAttributeMaxDynamicSharedMemorySize, GSMEM);

    dim3 blk(256);
    dim3 gHid(NHID / NT, NROWS / MT);    // (4, 64)
    dim3 gScr(NROWS / NT, NROWS / MT);   // (32, 64)

    // input splits (fp16 hi/lo)
    split2h<<<(NROWS * NSPIN) / 1024, blk>>>(x, xhi, xlo);
    split2h<<<(NHID * NSPIN) / 1024, blk>>>(Win, wihi, wilo);
    split2h<<<(NHID * NHID) / 1024, blk>>>(Wq, wqhi, wqlo);
    split2h<<<(NHID * NHID) / 1024, blk>>>(Wk, wkhi, wklo);
    split2h<<<(NHID * NHID) / 1024, blk>>>(Wv, wvhi, wvlo);

    // h = x @ Win^T + b  (3-term, fp16 split out)
    gemm_h<<<gHid, blk, GSMEM>>>(xhi, xlo, wihi, wilo, bin, nullptr, hhi, hlo,
                                 NROWS, NHID, NSPIN, 1.f, 3);
    // q = 0.25 * h @ Wq^T ; k = h @ Wk^T  (3-term, fp16 split out)
    gemm_h<<<gHid, blk, GSMEM>>>(hhi, hlo, wqhi, wqlo, nullptr, nullptr, qhi, qlo,
                                 NROWS, NHID, NHID, 0.25f, 3);
    gemm_h<<<gHid, blk, GSMEM>>>(hhi, hlo, wkhi, wklo, nullptr, nullptr, khi, klo,
                                 NROWS, NHID, NHID, 1.f, 3);
    // v = h @ Wv^T  (1-term, f32 out)
    gemm_h<<<gHid, blk, GSMEM>>>(hhi, hlo, wvhi, wvlo, nullptr, v, nullptr, nullptr,
                                 NROWS, NHID, NHID, 1.f, 1);
    // scores = q @ k^T  (3-term, f32 out)
    gemm_h<<<gScr, blk, GSMEM>>>(qhi, qlo, khi, klo, nullptr, s, nullptr, nullptr,
                                 NROWS, NROWS, NHID, 1.f, 3);
    // column softmax -> E' fp16 + 1/colsum
    colmax_part<<<dim3(NROWS / 256, 64), blk>>>(s, pt);
    colmax_fin <<<NROWS / 256, blk>>>(pt, cm);
    expsum_half<<<dim3(NROWS / 256, 64), blk>>>(s, eh, cm, pt);
    invsum_fin <<<NROWS / 256, blk>>>(pt, ic);
    // vth = fp16((v * 4096/c)^T)
    transpose_scale_h<<<dim3(NHID / 32, NROWS / 32), dim3(32, 8)>>>(v, ic, vth);
    // o = (1/4096) * E' @ vth^T  (1-term)
    gemm_h<<<gHid, blk, GSMEM>>>(eh, nullptr, vth, nullptr, nullptr, o,
                                 nullptr, nullptr, NROWS, NHID, NROWS, 1.f / 4096.f, 1);
    // per-row logcosh sum
    logcosh_rows<<<NROWS, blk>>>(o, out);
}

// round 8
// speedup vs baseline: 12.0973x; 1.2351x over previous
#include <cuda_runtime.h>
#include <cuda_fp16.h>
#include <cstdint>

#define NROWS 8192
#define NSPIN 1024
#define NHID  1024
#define MT    128
#define NT    256

// ------------------------ scratch (device globals) ------------------------
__device__ __half g_xhi[(size_t)NROWS * NSPIN];
__device__ __half g_xlo[(size_t)NROWS * NSPIN];
__device__ __half g_wihi[(size_t)NHID * NSPIN];
__device__ __half g_wilo[(size_t)NHID * NSPIN];
__device__ __half g_wqhi[(size_t)NHID * NHID];
__device__ __half g_wqlo[(size_t)NHID * NHID];
__device__ __half g_wkhi[(size_t)NHID * NHID];
__device__ __half g_wklo[(size_t)NHID * NHID];
__device__ __half g_wvhi[(size_t)NHID * NHID];
__device__ __half g_wvlo[(size_t)NHID * NHID];
__device__ __half g_hhi[(size_t)NROWS * NHID];
__device__ __half g_hlo[(size_t)NROWS * NHID];
__device__ __half g_qhi[(size_t)NROWS * NHID];
__device__ __half g_qlo[(size_t)NROWS * NHID];
__device__ __half g_khi[(size_t)NROWS * NHID];
__device__ __half g_klo[(size_t)NROWS * NHID];
__device__ float  g_v  [(size_t)NROWS * NHID];
__device__ __half g_vth[(size_t)NHID * NROWS];   // (v * 4096/c)^T
__device__ float  g_s  [(size_t)NROWS * NROWS];  // scores f32
__device__ __half g_eh [(size_t)NROWS * NROWS];  // E' = 4096*exp(s-m)
__device__ float  g_o  [(size_t)NROWS * NHID];
__device__ float  g_cm [NROWS];
__device__ float  g_pt [(size_t)64 * NROWS];
__device__ float  g_ic [NROWS];

#define SM103A_PATH (defined(__CUDA_ARCH__) && defined(__CUDA_ARCH_FEAT_SM103_ALL))

#if SM103A_PATH
__device__ __forceinline__ uint32_t smem_u32(const void* p) {
    uint32_t a;
    asm("{ .reg .u64 t; cvta.to.shared.u64 t, %1; cvt.u32.u64 %0, t; }"
        : "=r"(a) : "l"(p));
    return a;
}
__device__ __forceinline__ uint32_t elect_one() {
    uint32_t p;
    asm volatile("{\n\t.reg .pred p;\n\telect.sync _|p, 0xFFFFFFFF;\n\t"
                 "selp.b32 %0, 1, 0, p;\n\t}" : "=r"(p));
    return p;
}
__device__ __forceinline__ uint32_t swz128(uint32_t off) {
    return off ^ ((off >> 3) & 0x70);
}
// cg2 fp16 MMA, M=256 across the CTA pair
__device__ __forceinline__ void mma_f16_cg2(uint32_t d, uint64_t a, uint64_t b,
                                            uint32_t idesc, uint32_t en) {
    asm volatile("{\n\t.reg .pred p;\n\tsetp.ne.u32 p, %4, 0;\n\t"
                 "tcgen05.mma.cta_group::2.kind::f16 [%0], %1, %2, %3, p;\n\t}"
                 :: "r"(d), "l"(a), "l"(b), "r"(idesc), "r"(en) : "memory");
}
__device__ __forceinline__ void cpa16(uint32_t dst, const void* src) {
    asm volatile("cp.async.cg.shared.global [%0], [%1], 16;"
                 :: "r"(dst), "l"(src) : "memory");
}
#define CP_COMMIT() asm volatile("cp.async.commit_group;" ::: "memory")
#define CP_WAIT1()  asm volatile("cp.async.wait_group 1;" ::: "memory")
#define TC_ALLOC_CG2(sa, n) \
    asm volatile("tcgen05.alloc.cta_group::2.sync.aligned.shared::cta.b32 [%0], %1;" \
                 :: "r"(sa), "r"(n) : "memory")
#define TC_RELINQ_CG2() \
    asm volatile("tcgen05.relinquish_alloc_permit.cta_group::2.sync.aligned;")
#define TC_DEALLOC_CG2(t, n) \
    asm volatile("tcgen05.dealloc.cta_group::2.sync.aligned.b32 %0, %1;" :: "r"(t), "r"(n))
#define TC_COMMIT_MC_CG2(mb) \
    asm volatile("tcgen05.commit.cta_group::2.mbarrier::arrive::one.shared::cluster.multicast::cluster.b64 [%0], %1;" \
                 :: "r"(mb), "h"((uint16_t)0x3) : "memory")
#define TC_FENCE_AFTER()  asm volatile("tcgen05.fence::after_thread_sync;" ::: "memory")
#define TC_WAIT_LD()      asm volatile("tcgen05.wait::ld.sync.aligned;" ::: "memory")
#define FENCE_ASYNC()     asm volatile("fence.proxy.async.shared::cta;" ::: "memory")
#define MBAR_INIT(mb, c) \
    asm volatile("mbarrier.init.shared.b64 [%0], %1;" :: "r"(mb), "r"(c) : "memory")
#define MBAR_ARRIVE(mb) \
    asm volatile("mbarrier.arrive.shared.b64 _, [%0];" :: "r"(mb) : "memory")
#define MBAR_ARRIVE_REMOTE(mb, rk) \
    asm volatile("{\n\t.reg .b32 ra;\n\tmapa.shared::cluster.u32 ra, %0, %1;\n\t" \
                 "mbarrier.arrive.shared::cluster.b64 _, [ra];\n\t}" \
                 :: "r"(mb), "r"(rk) : "memory")
#define MBAR_WAIT(mb, par) do {                                                  \
    asm volatile("{\n\t.reg .pred P1;\n\t"                                       \
                 "WAIT_LOOP_%=:\n\t"                                             \
                 "mbarrier.try_wait.parity.acquire.cta.shared::cta.b64 P1, [%0], %1, 0x989680;\n\t" \
                 "@P1 bra.uni WAIT_DONE_%=;\n\t"                                 \
                 "bra.uni WAIT_LOOP_%=;\n\t"                                     \
                 "WAIT_DONE_%=:\n\t}"                                            \
                 :: "r"(mb), "r"(par) : "memory");                               \
} while (0)
#define MBAR_WAIT_CL(mb, par) do {                                               \
    asm volatile("{\n\t.reg .pred P1;\n\t"                                       \
                 "WAIT_LOOP_%=:\n\t"                                             \
                 "mbarrier.try_wait.parity.acquire.cluster.shared::cta.b64 P1, [%0], %1, 0x989680;\n\t" \
                 "@P1 bra.uni WAIT_DONE_%=;\n\t"                                 \
                 "bra.uni WAIT_LOOP_%=;\n\t"                                     \
                 "WAIT_DONE_%=:\n\t}"                                            \
                 :: "r"(mb), "r"(par) : "memory");                               \
} while (0)
#define CLUSTER_SYNC() do { \
    asm volatile("barrier.cluster.arrive.aligned;" ::: "memory"); \
    asm volatile("barrier.cluster.wait.aligned;" ::: "memory"); \
} while (0)

__device__ __forceinline__ void ldtm32(uint32_t* r, uint32_t addr) {
    asm volatile(
        "tcgen05.ld.sync.aligned.32x32b.x32.b32 "
        "{%0, %1, %2, %3, %4, %5, %6, %7, "
        " %8, %9, %10, %11, %12, %13, %14, %15, "
        " %16, %17, %18, %19, %20, %21, %22, %23, "
        " %24, %25, %26, %27, %28, %29, %30, %31}, [%32];"
        : "=r"(r[0]),  "=r"(r[1]),  "=r"(r[2]),  "=r"(r[3]),
          "=r"(r[4]),  "=r"(r[5]),  "=r"(r[6]),  "=r"(r[7]),
          "=r"(r[8]),  "=r"(r[9]),  "=r"(r[10]), "=r"(r[11]),
          "=r"(r[12]), "=r"(r[13]), "=r"(r[14]), "=r"(r[15]),
          "=r"(r[16]), "=r"(r[17]), "=r"(r[18]), "=r"(r[19]),
          "=r"(r[20]), "=r"(r[21]), "=r"(r[22]), "=r"(r[23]),
          "=r"(r[24]), "=r"(r[25]), "=r"(r[26]), "=r"(r[27]),
          "=r"(r[28]), "=r"(r[29]), "=r"(r[30]), "=r"(r[31])
        : "r"(addr));
}
// SMEM descriptor: SW128, Blackwell version=1, LBO=1, SBO=64 (K-major)
__device__ __forceinline__ uint64_t smem_desc(uint32_t addr) {
    return ((uint64_t)2 << 61) | ((uint64_t)1 << 46) | ((uint64_t)64 << 32) |
           ((uint64_t)1 << 16) | ((uint64_t)(addr >> 4) & 0x3FFF);
}
// idesc: dtype=f32, a=b=fp16, N=256, M=256 (cg2), K-major
#define IDESC_F16_CG2 ((1u << 4) | (32u << 17) | (16u << 24))
#endif  // SM103A_PATH

// SMEM layout: [tmem_ptr][cmt0..2][ready0..2] then 3 buffers of
// [Ahi 16K][Alo 16K][Bhi 16K][Blo 16K]  (B holds this CTA's 128-row half)
#define SM_TMEMP  0
#define SM_CMT    16
#define SM_RDY    48
#define SM_TILES  1024
#define TILEB     16384
#define BUFB      (4 * TILEB)                // 65536
#define GSMEM     (SM_TILES + 3 * BUFB)      // 197632

// ==========================================================================
// fp16 3-term GEMM on cg2 (2-CTA) MMA: C = alpha * A @ B^T (+bias).
// Cluster (2,1,1) on a FLAT grid: blockIdx.x = pair*2 + rank.
// pair -> (mtile, ntile); CTA covers m0 = mtile*256 + rank*128 (its A rows +
// its TMEM D half) and loads B rows [n0 + rank*128, +128).
// terms=3: hi*hi + hi*lo + lo*hi.  Grid: 2*(M/256)*(N/256) CTAs, 256 thr.
// K % 64 == 0, K/64 >= 3, M % 256 == 0.
// ==========================================================================
__global__ void __launch_bounds__(256, 1) __cluster_dims__(2, 1, 1)
gemm_h(const __half* __restrict__ Ahi, const __half* __restrict__ Alo,
       const __half* __restrict__ Bhi, const __half* __restrict__ Blo,
       const float* __restrict__ bias, float* __restrict__ C,
       __half* __restrict__ Chi, __half* __restrict__ Clo,
       int M, int N, int K, float alpha, int terms) {
#if SM103A_PATH
    extern __shared__ char smem[];
    const uint32_t sb = smem_u32(smem);
    const int tid = threadIdx.x;
    const int wid = tid >> 5;
    const int lid = tid & 31;
    const int ntiles = N / NT;
    const int rank = (int)(blockIdx.x & 1);          // cg2 pair rank
    const int pair = (int)(blockIdx.x >> 1);
    const int mtile = pair / ntiles;
    const int ntile = pair % ntiles;
    const int m0 = mtile * 256 + rank * MT;          // this CTA's 128 A rows
    const int n0 = ntile * NT;
    const int brow0 = n0 + rank * 128;               // this CTA's B half
    const bool full = (terms == 3);

    if (wid == 0) { TC_ALLOC_CG2(sb + SM_TMEMP, 256); TC_RELINQ_CG2(); }
    if (tid == 0) {
        #pragma unroll
        for (int b = 0; b < 3; b++) {
            MBAR_INIT(sb + SM_CMT + 8 * b, 1);
            MBAR_INIT(sb + SM_RDY + 8 * b, 2);
        }
    }
    __syncthreads();
    CLUSTER_SYNC();   // barriers + alloc visible cluster-wide

    uint32_t tmem;
    asm volatile("ld.shared.b32 %0, [%1];" : "=r"(tmem) : "r"(sb + SM_TMEMP));

    // per-thread load mapping: 4 x 16B per tensor per stage (128 rows x 128B)
    uint32_t soff[4];
    const __half *pAh[4], *pAl[4], *pBh[4], *pBl[4];
    #pragma unroll
    for (int i = 0; i < 4; i++) {
        int idx = tid + 256 * i, r = idx >> 3, c = idx & 7;
        soff[i] = swz128((uint32_t)(r * 128 + c * 16));
        size_t ga = (size_t)(m0 + r) * K + c * 8;
        size_t gb = (size_t)(brow0 + r) * K + c * 8;
        pAh[i] = Ahi + ga;  pAl[i] = full ? Alo + ga : nullptr;
        pBh[i] = Bhi + gb;  pBl[i] = full ? Blo + gb : nullptr;
    }

    const int nk = K / 64;

    // prologue: stages 0 and 1
    #pragma unroll
    for (int s = 0; s < 2; s++) {
        uint32_t bb = sb + SM_TILES + s * BUFB;
        const int off = s * 64;
        #pragma unroll
        for (int i = 0; i < 4; i++) {
            cpa16(bb + soff[i], pAh[i] + off);
            if (full) cpa16(bb + TILEB + soff[i], pAl[i] + off);
            cpa16(bb + 2 * TILEB + soff[i], pBh[i] + off);
            if (full) cpa16(bb + 3 * TILEB + soff[i], pBl[i] + off);
        }
        CP_COMMIT();
    }

    for (int k0 = 0; k0 < nk; k0++) {
        const int b = k0 % 3;
        CP_WAIT1();                 // stage k0 loads complete
        FENCE_ASYNC();
        __syncthreads();

        // signal "this CTA's half of stage k0 is resident" to the leader
        if (tid == 0) {
            if (rank == 0) MBAR_ARRIVE(sb + SM_RDY + 8 * b);
            else           MBAR_ARRIVE_REMOTE(sb + SM_RDY + 8 * b, 0);
        }

        if (rank == 0 && wid == 0) {
            if (elect_one()) {
                MBAR_WAIT_CL(sb + SM_RDY + 8 * b, (k0 / 3) & 1);
                uint32_t tb = sb + SM_TILES + b * BUFB;
                uint64_t dAh = smem_desc(tb);
                uint64_t dAl = smem_desc(tb + TILEB);
                uint64_t dBh = smem_desc(tb + 2 * TILEB);
                uint64_t dBl = smem_desc(tb + 3 * TILEB);
                #pragma unroll
                for (int s = 0; s < 4; s++)
                    mma_f16_cg2(tmem, dAh + 2 * s, dBh + 2 * s, IDESC_F16_CG2,
                                (k0 > 0 || s > 0) ? 1u : 0u);
                if (full) {
                    #pragma unroll
                    for (int s = 0; s < 4; s++)
                        mma_f16_cg2(tmem, dAh + 2 * s, dBl + 2 * s, IDESC_F16_CG2, 1u);
                    #pragma unroll
                    for (int s = 0; s < 4; s++)
                        mma_f16_cg2(tmem, dAl + 2 * s, dBh + 2 * s, IDESC_F16_CG2, 1u);
                }
                TC_COMMIT_MC_CG2(sb + SM_CMT + 8 * b);
            }
        }

        if (k0 + 2 < nk) {
            const int b2 = (k0 + 2) % 3;
            // buffer b2 was used by stage k0-1: wait its (multicast) commit
            if (k0 >= 1)
                MBAR_WAIT(sb + SM_CMT + 8 * b2, ((k0 - 1) / 3) & 1);
            uint32_t bb = sb + SM_TILES + b2 * BUFB;
            const int off = (k0 + 2) * 64;
            #pragma unroll
            for (int i = 0; i < 4; i++) {
                cpa16(bb + soff[i], pAh[i] + off);
                if (full) cpa16(bb + TILEB + soff[i], pAl[i] + off);
                cpa16(bb + 2 * TILEB + soff[i], pBh[i] + off);
                if (full) cpa16(bb + 3 * TILEB + soff[i], pBl[i] + off);
            }
        }
        CP_COMMIT();   // always commit (possibly empty group) to keep counts
    }

    // wait final commit (in-order completion)
    MBAR_WAIT(sb + SM_CMT + 8 * ((nk - 1) % 3), ((nk - 1) / 3) & 1);
    TC_FENCE_AFTER();

    // epilogue: each CTA reads its own TMEM half (its 128 M-rows)
    if (wid < 4) {
        const int r = m0 + wid * 32 + lid;
        #pragma unroll
        for (int g = 0; g < 8; g++) {
            uint32_t d[32];
            ldtm32(d, tmem + g * 32);
            TC_WAIT_LD();
            const int c0 = n0 + g * 32;
            float vals[32];
            #pragma unroll
            for (int j = 0; j < 32; j++) {
                float v = __uint_as_float(d[j]) * alpha;
                if (bias) v += bias[c0 + j];
                vals[j] = v;
            }
            if (C) {
                float* crow = C + (size_t)r * N + c0;
                #pragma unroll
                for (int j = 0; j < 8; j++)
                    *(float4*)(crow + 4 * j) = make_float4(
                        vals[4 * j], vals[4 * j + 1], vals[4 * j + 2], vals[4 * j + 3]);
            }
            if (Chi) {
                __half* hrow = Chi + (size_t)r * N + c0;
                __half* lrow = Clo + (size_t)r * N + c0;
                #pragma unroll
                for (int j = 0; j < 16; j++) {
                    float v0 = vals[2 * j], v1 = vals[2 * j + 1];
                    __half h0 = __float2half(v0), h1 = __float2half(v1);
                    __half l0 = __float2half(v0 - __half2float(h0));
                    __half l1 = __float2half(v1 - __half2float(h1));
                    *(__half2*)(hrow + 2 * j) = __halves2half2(h0, h1);
                    *(__half2*)(lrow + 2 * j) = __halves2half2(l0, l1);
                }
            }
        }
    }
    __syncthreads();
    CLUSTER_SYNC();   // both CTAs done with all SMEM/TMEM traffic
    if (wid == 0) TC_DEALLOC_CG2(tmem, 256);
    CLUSTER_SYNC();

#else  // fallback (compile-only for plain compute_103 pass)
    const int tid = threadIdx.x;
    const int ntiles = N / NT;
    const int rank = (int)(blockIdx.x & 1);
    const int pair = (int)(blockIdx.x >> 1);
    const int m0 = (pair / ntiles) * 256 + rank * MT;
    const int n0 = (pair % ntiles) * NT;
    int r = m0 + (tid & 127);
    int cb = n0 + (tid >> 7) * 128;
    for (int j = 0; j < 128; j++) {
        int c = cb + j;
        float acc = 0.f;
        for (int kk = 0; kk < K; kk++) {
            float a = __half2float(Ahi[(size_t)r * K + kk]) +
                      (terms == 3 ? __half2float(Alo[(size_t)r * K + kk]) : 0.f);
            float b = __half2float(Bhi[(size_t)c * K + kk]) +
                      (terms == 3 ? __half2float(Blo[(size_t)c * K + kk]) : 0.f);
            acc += a * b;
        }
        float v = acc * alpha + (bias ? bias[c] : 0.f);
        if (C) C[(size_t)r * N + c] = v;
        if (Chi) {
            __half h = __float2half(v);
            Chi[(size_t)r * N + c] = h;
            Clo[(size_t)r * N + c] = __float2half(v - __half2float(h));
        }
    }
#endif
}

// ==========================================================================
// elementwise split f32 -> fp16 hi/lo
// ==========================================================================
__global__ void split2h(const float* __restrict__ in, __half* __restrict__ hi,
                        __half* __restrict__ lo) {
    size_t i = ((size_t)blockIdx.x * 256 + threadIdx.x) * 4;
    float4 v = *(const float4*)(in + i);
    __half h0 = __float2half(v.x), h1 = __float2half(v.y);
    __half h2 = __float2half(v.z), h3 = __float2half(v.w);
    __half2 hh0 = __halves2half2(h0, h1), hh1 = __halves2half2(h2, h3);
    __half2 ll0 = __halves2half2(__float2half(v.x - __half2float(h0)),
                                 __float2half(v.y - __half2float(h1)));
    __half2 ll1 = __halves2half2(__float2half(v.z - __half2float(h2)),
                                 __float2half(v.w - __half2float(h3)));
    *(__half2*)(hi + i) = hh0;
    *(__half2*)(hi + i + 2) = hh1;
    *(__half2*)(lo + i) = ll0;
    *(__half2*)(lo + i + 2) = ll1;
}

// ==========================================================================
// Column softmax (axis 0)
// ==========================================================================
#define ROWS_PER_BLK 128

__global__ void colmax_part(const float* __restrict__ S, float* __restrict__ part) {
    int j = blockIdx.x * 256 + threadIdx.x;
    int r0 = blockIdx.y * ROWS_PER_BLK;
    const float* p = S + (size_t)r0 * NROWS + j;
    float m = -3.402823e38f;
    #pragma unroll 8
    for (int i = 0; i < ROWS_PER_BLK; i++)
        m = fmaxf(m, p[(size_t)i * NROWS]);
    part[(size_t)blockIdx.y * NROWS + j] = m;
}

__global__ void colmax_fin(const float* __restrict__ part, float* __restrict__ cm) {
    int j = blockIdx.x * 256 + threadIdx.x;
    float m = -3.402823e38f;
    #pragma unroll
    for (int i = 0; i < 64; i++)
        m = fmaxf(m, part[(size_t)i * NROWS + j]);
    cm[j] = m;
}

// E' = 2^12 * exp(s - m) via ex2.approx.f16x2; partial column sums of E'
__global__ void expsum_half(const float* __restrict__ S, __half* __restrict__ E,
                            const float* __restrict__ cm, float* __restrict__ part) {
    int j = blockIdx.x * 256 + threadIdx.x;
    int r0 = blockIdx.y * ROWS_PER_BLK;
    const float* p = S + (size_t)r0 * NROWS + j;
    __half* pe = E + (size_t)r0 * NROWS + j;
    float mj = cm[j];
    const float L2E = 1.4426950408889634f;
    float c = 0.f;
    #pragma unroll 4
    for (int i = 0; i < ROWS_PER_BLK; i += 2) {
        float t0 = (p[(size_t)i * NROWS] - mj) * L2E + 12.f;
        float t1 = (p[(size_t)(i + 1) * NROWS] - mj) * L2E + 12.f;
        __half2 he = h2exp2(__floats2half2_rn(t0, t1));
        pe[(size_t)i * NROWS] = __low2half(he);
        pe[(size_t)(i + 1) * NROWS] = __high2half(he);
        float2 f = __half22float2(he);
        c += f.x + f.y;
    }
    part[(size_t)blockIdx.y * NROWS + j] = c;
}

__global__ void invsum_fin(const float* __restrict__ part, float* __restrict__ ic) {
    int j = blockIdx.x * 256 + threadIdx.x;
    float c = 0.f;
    #pragma unroll
    for (int i = 0; i < 64; i++)
        c += part[(size_t)i * NROWS + j];
    ic[j] = 1.f / c;
}

// ==========================================================================
// vth[n,k] = fp16( v[k,n] * 4096 * ic[k] )
// ==========================================================================
__global__ void transpose_scale_h(const float* __restrict__ V,
                                  const float* __restrict__ ic,
                                  __half* __restrict__ VT) {
    __shared__ float t[32][33];
    int n = blockIdx.x * 32 + threadIdx.x;
    int k = blockIdx.y * 32 + threadIdx.y;
    #pragma unroll
    for (int i = 0; i < 32; i += 8)
        t[threadIdx.y + i][threadIdx.x] =
            V[(size_t)(k + i) * NHID + n] * (4096.f * ic[k + i]);
    __syncthreads();
    int ko = blockIdx.y * 32 + threadIdx.x;
    int no = blockIdx.x * 32 + threadIdx.y;
    #pragma unroll
    for (int i = 0; i < 32; i += 8)
        VT[(size_t)(no + i) * NROWS + ko] = __float2half(t[threadIdx.x][threadIdx.y + i]);
}

// ==========================================================================
// out[i] = sum_h logcosh(O[i,h])
// ==========================================================================
__global__ void logcosh_rows(const float* __restrict__ O, float* __restrict__ out) {
    __shared__ float red[256];
    int row = blockIdx.x;
    const float* o = O + (size_t)row * NHID;
    int t = threadIdx.x;
    float a0 = fabsf(o[t]);
    float a1 = fabsf(o[t + 256]);
    float a2 = fabsf(o[t + 512]);
    float a3 = fabsf(o[t + 768]);
    const float N2L2E = -2.f * 1.4426950408889634f;
    __half2 w01 = h2exp2(__floats2half2_rn(a0 * N2L2E, a1 * N2L2E));
    __half2 w23 = h2exp2(__floats2half2_rn(a2 * N2L2E, a3 * N2L2E));
    float2 f01 = __half22float2(w01), f23 = __half22float2(w23);
    const float LN2 = 0.69314718055994531f;
    float s = a0 + a1 + a2 + a3 +
              LN2 * (__log2f(1.f + f01.x) + __log2f(1.f + f01.y) +
                     __log2f(1.f + f23.x) + __log2f(1.f + f23.y));
    red[t] = s;
    __syncthreads();
    for (int st = 128; st > 0; st >>= 1) {
        if (t < st) red[t] += red[t + st];
        __syncthreads();
    }
    if (t == 0)
        out[row] = red[0] - (float)NHID * LN2;
}

// ==========================================================================
extern "C" void kernel_launch(void* const* d_in, const int* in_sizes, int n_in,
                              void* d_out, int out_size) {
    const float* x   = (const float*)d_in[0];
    const float* Win = (const float*)d_in[1];
    const float* bin = (const float*)d_in[2];
    const float* Wq  = (const float*)d_in[3];
    const float* Wk  = (const float*)d_in[4];
    const float* Wv  = (const float*)d_in[5];
    float* out = (float*)d_out;

    __half *xhi, *xlo, *wihi, *wilo, *wqhi, *wqlo, *wkhi, *wklo, *wvhi, *wvlo;
    __half *hhi, *hlo, *qhi, *qlo, *khi, *klo, *vth, *eh;
    float *v, *s, *o, *cm, *pt, *ic;
    cudaGetSymbolAddress((void**)&xhi,  g_xhi);
    cudaGetSymbolAddress((void**)&xlo,  g_xlo);
    cudaGetSymbolAddress((void**)&wihi, g_wihi);
    cudaGetSymbolAddress((void**)&wilo, g_wilo);
    cudaGetSymbolAddress((void**)&wqhi, g_wqhi);
    cudaGetSymbolAddress((void**)&wqlo, g_wqlo);
    cudaGetSymbolAddress((void**)&wkhi, g_wkhi);
    cudaGetSymbolAddress((void**)&wklo, g_wklo);
    cudaGetSymbolAddress((void**)&wvhi, g_wvhi);
    cudaGetSymbolAddress((void**)&wvlo, g_wvlo);
    cudaGetSymbolAddress((void**)&hhi,  g_hhi);
    cudaGetSymbolAddress((void**)&hlo,  g_hlo);
    cudaGetSymbolAddress((void**)&qhi,  g_qhi);
    cudaGetSymbolAddress((void**)&qlo,  g_qlo);
    cudaGetSymbolAddress((void**)&khi,  g_khi);
    cudaGetSymbolAddress((void**)&klo,  g_klo);
    cudaGetSymbolAddress((void**)&v,    g_v);
    cudaGetSymbolAddress((void**)&vth,  g_vth);
    cudaGetSymbolAddress((void**)&s,    g_s);
    cudaGetSymbolAddress((void**)&eh,   g_eh);
    cudaGetSymbolAddress((void**)&o,    g_o);
    cudaGetSymbolAddress((void**)&cm,   g_cm);
    cudaGetSymbolAddress((void**)&pt,   g_pt);
    cudaGetSymbolAddress((void**)&ic,   g_ic);

    cudaFuncSetAttribute(gemm_h, cudaFuncAttributeMaxDynamicSharedMemorySize, GSMEM);

    dim3 blk(256);
    // flat grids: 2 CTAs per (256-M x 256-N) tile
    const int gHid = 2 * (NROWS / 256) * (NHID / 256);    // 256
    const int gScr = 2 * (NROWS / 256) * (NROWS / 256);   // 2048

    // input splits (fp16 hi/lo)
    split2h<<<(NROWS * NSPIN) / 1024, blk>>>(x, xhi, xlo);
    split2h<<<(NHID * NSPIN) / 1024, blk>>>(Win, wihi, wilo);
    split2h<<<(NHID * NHID) / 1024, blk>>>(Wq, wqhi, wqlo);
    split2h<<<(NHID * NHID) / 1024, blk>>>(Wk, wkhi, wklo);
    split2h<<<(NHID * NHID) / 1024, blk>>>(Wv, wvhi, wvlo);

    // h = x @ Win^T + b  (3-term, fp16 split out)
    gemm_h<<<gHid, blk, GSMEM>>>(xhi, xlo, wihi, wilo, bin, nullptr, hhi, hlo,
                                 NROWS, NHID, NSPIN, 1.f, 3);
    // q = 0.25 * h @ Wq^T ; k = h @ Wk^T  (3-term, fp16 split out)
    gemm_h<<<gHid, blk, GSMEM>>>(hhi, hlo, wqhi, wqlo, nullptr, nullptr, qhi, qlo,
                                 NROWS, NHID, NHID, 0.25f, 3);
    gemm_h<<<gHid, blk, GSMEM>>>(hhi, hlo, wkhi, wklo, nullptr, nullptr, khi, klo,
                                 NROWS, NHID, NHID, 1.f, 3);
    // v = h @ Wv^T  (1-term, f32 out)
    gemm_h<<<gHid, blk, GSMEM>>>(hhi, hlo, wvhi, wvlo, nullptr, v, nullptr, nullptr,
                                 NROWS, NHID, NHID, 1.f, 1);
    // scores = q @ k^T  (3-term, f32 out)
    gemm_h<<<gScr, blk, GSMEM>>>(qhi, qlo, khi, klo, nullptr, s, nullptr, nullptr,
                                 NROWS, NROWS, NHID, 1.f, 3);
    // column softmax -> E' fp16 + 1/colsum
    colmax_part<<<dim3(NROWS / 256, 64), blk>>>(s, pt);
    colmax_fin <<<NROWS / 256, blk>>>(pt, cm);
    expsum_half<<<dim3(NROWS / 256, 64), blk>>>(s, eh, cm, pt);
    invsum_fin <<<NROWS / 256, blk>>>(pt, ic);
    // vth = fp16((v * 4096/c)^T)
    transpose_scale_h<<<dim3(NHID / 32, NROWS / 32), dim3(32, 8)>>>(v, ic, vth);
    // o = (1/4096) * E' @ vth^T  (1-term)
    gemm_h<<<gHid, blk, GSMEM>>>(eh, nullptr, vth, nullptr, nullptr, o,
                                 nullptr, nullptr, NROWS, NHID, NROWS, 1.f / 4096.f, 1);
    // per-row logcosh sum
    logcosh_rows<<<NROWS, blk>>>(o, out);
}